// round 7
// baseline (speedup 1.0000x reference)
#include <cuda_runtime.h>
#include <math.h>

#define IMH 256
#define IMW 320
#define HWSZ (IMH*IMW)
#define BB 4
#define NCT 161

// ---------------- scratch (device globals; no allocation allowed) ----------
__device__ float g_z [BB*32*HWSZ];
__device__ float g_rh[BB*32*HWSZ];
__device__ float g_d1[BB*32*HWSZ];
// transposed weights: layout [(ic*9+tap)*32 + oc]
__device__ float g_wtz[NCT*9*32];
__device__ float g_wtr[NCT*9*32];
__device__ float g_wtq[NCT*9*32];
__device__ float g_wtd[32*9*32];
__device__ float g_wtc[32*9*32];
__device__ float g_wt2[32*64];    // dh2^T  [ic][oc2]
__device__ float g_wt3[64*256];   // dh3^T  [ic][oc]

__device__ __forceinline__ float sigmoidf_(float v){ return 1.f/(1.f+__expf(-v)); }

// ---- packed fp32x2 helpers (sm_103a FFMA2 — PTX-only) ---------------------
__device__ __forceinline__ unsigned long long pack2(float a, float b){
  unsigned long long r; asm("mov.b64 %0,{%1,%2};":"=l"(r):"f"(a),"f"(b)); return r;
}
__device__ __forceinline__ void ffma2(unsigned long long& d, unsigned long long a, unsigned long long b){
  asm("fma.rn.f32x2 %0, %1, %2, %0;":"+l"(d):"l"(a),"l"(b));
}
__device__ __forceinline__ float2 unpack2(unsigned long long v){
  float2 r; asm("mov.b64 {%0,%1}, %2;":"=f"(r.x),"=f"(r.y):"l"(v)); return r;
}

// ---- cp.async helpers -----------------------------------------------------
__device__ __forceinline__ void cp_async4(float* smem_dst, const float* gsrc, bool valid){
  unsigned int d = (unsigned int)__cvta_generic_to_shared(smem_dst);
  int sz = valid ? 4 : 0;
  asm volatile("cp.async.ca.shared.global [%0], [%1], 4, %2;\n" :: "r"(d), "l"(gsrc), "r"(sz));
}
__device__ __forceinline__ void cp_commit(){ asm volatile("cp.async.commit_group;\n"); }
template<int N> __device__ __forceinline__ void cp_wait(){ asm volatile("cp.async.wait_group %0;\n"::"n"(N)); }

// ---------------- weight transforms ---------------------------------------
__global__ void wtrans_kernel(const float* __restrict__ Wz, const float* __restrict__ Wr,
                              const float* __restrict__ Wq, const float* __restrict__ dh1,
                              const float* __restrict__ ch1, const float* __restrict__ dh2,
                              const float* __restrict__ dh3){
  int t = blockIdx.y;
  int idx = blockIdx.x*256 + threadIdx.x;
  if (t < 5){
    const float* src; float* dst; int cin;
    if      (t==0){src=Wz;  dst=g_wtz; cin=NCT;}
    else if (t==1){src=Wr;  dst=g_wtr; cin=NCT;}
    else if (t==2){src=Wq;  dst=g_wtq; cin=NCT;}
    else if (t==3){src=dh1; dst=g_wtd; cin=32;}
    else          {src=ch1; dst=g_wtc; cin=32;}
    int n = cin*288;
    if (idx < n){
      int ic = idx/288; int r = idx - ic*288; int tap = r>>5; int oc = r&31;
      dst[idx] = src[(oc*cin+ic)*9+tap];
    }
  } else if (t==5){
    if (idx < 2048) g_wt2[idx] = dh2[(idx&63)*32 + (idx>>6)];
  } else {
    if (idx < 16384) g_wt3[idx] = dh3[(idx&255)*64 + (idx>>8)];
  }
}

// ============= pipelined 3x3 conv, f32x2, 256 thr, 4px x 16oc =============
// MODE 0: z = sigmoid(conv(hx,Wz)+bz)                -> g_z
// MODE 1: rh = sigmoid(conv(hx,Wr)+br)*hidden        -> g_rh
// MODE 2: q = tanh(conv([rh;x],Wq)+bq); h=(1-z)h+zq  -> out
// MODE 3: c1=relu(conv(h,ch1,dil2)); c0=ch2.c1+cb2   -> out(c0), out2(conf)
// MODE 4: d1=relu(conv(h,dh1,dil2))                  -> g_d1
template<int MODE>
__global__ void __launch_bounds__(256,2) conv_pipe(
    const float* __restrict__ in_h, const float* __restrict__ depth,
    const float* __restrict__ corr, const float* __restrict__ bias,
    const float* __restrict__ hidden,
    const float* __restrict__ aux, const float* __restrict__ aux2,
    float* __restrict__ out, float* __restrict__ out2)
{
  constexpr int CIN = (MODE<3)?NCT:32;
  constexpr int DIL = (MODE<3)?1:2;
  constexpr int SH  = 16+2*DIL;
  constexpr int SW  = 32+2*DIL;
  constexpr int CH  = 8;
  constexpr int TILE = CH*SH*SW;
  constexpr int WCH  = CH*288;
  constexpr int NC   = (CIN+CH-1)/CH;

  extern __shared__ float sm[];
  float* s_in  = sm;                 // 2*TILE
  float* s_w   = sm + 2*TILE;        // 2*WCH
  float* s_red = s_w + 2*WCH;        // 512 (MODE 3 only)

  const int tid = threadIdx.x;
  const int x   = tid & 31;
  const int ty  = (tid >> 5) & 3;
  const int oh  = tid >> 7;
  const int ty4 = ty*4;
  const int x0  = blockIdx.x*32;
  const int y0  = blockIdx.y*16;
  const int b   = blockIdx.z;

  const float* i0 = (MODE==2) ? (const float*)g_rh : in_h;
  const float* WtT;
  if      (MODE==0) WtT = g_wtz;
  else if (MODE==1) WtT = g_wtr;
  else if (MODE==2) WtT = g_wtq;
  else if (MODE==3) WtT = g_wtc;
  else              WtT = g_wtd;

  // prefetch one chunk into buffer `buf`
  auto prefetch = [&](int cc, int buf){
    int c0 = cc*CH;
    float* din = s_in + buf*TILE;
    float* dw  = s_w  + buf*WCH;
    for (int idx = tid; idx < TILE; idx += 256){
      int icl = idx/(SH*SW);
      int rem = idx - icl*(SH*SW);
      int sy  = rem/SW;
      int sx  = rem - sy*SW;
      int c   = c0+icl;
      int gy  = y0 + sy - DIL;
      int gx  = x0 + sx - DIL;
      bool ok = (c < CIN) && ((unsigned)gy < IMH) && ((unsigned)gx < IMW);
      int cs  = ok ? c : 0;
      const float* p;
      if (MODE>=3)      p = in_h + (size_t)(b*32 + cs)*HWSZ;
      else if (cs < 32) p = i0   + (size_t)(b*32 + cs)*HWSZ;
      else if (cs == 32)p = depth+ (size_t)b*HWSZ;
      else              p = corr + (size_t)(b*128 + (cs-33))*HWSZ;
      int off = ok ? (gy*IMW + gx) : 0;
      cp_async4(din + idx, p + off, ok);
    }
    int wbase = c0*288;
    for (int idx = tid; idx < WCH; idx += 256){
      bool ok = (wbase + idx) < CIN*288;
      cp_async4(dw + idx, WtT + (ok ? wbase+idx : 0), ok);
    }
  };

  unsigned long long acc[4][8];
  #pragma unroll
  for (int j=0;j<4;j++)
    #pragma unroll
    for (int o=0;o<8;o++) acc[j][o] = 0ull;

  prefetch(0, 0); cp_commit();

  for (int cc=0; cc<NC; cc++){
    if (cc+1 < NC){ prefetch(cc+1, (cc+1)&1); cp_commit(); cp_wait<1>(); }
    else          { cp_wait<0>(); }
    __syncthreads();

    const float* sin = s_in + (cc&1)*TILE;
    const float* sw  = s_w  + (cc&1)*WCH;

    if (MODE < 3){
      // register row-cache: 18 distinct pixel values per input channel.
      // icl unroll capped at 2 to keep ptxas compile time bounded.
      #pragma unroll 2
      for (int icl=0; icl<CH; icl++){
        const float* base = sin + icl*(SH*SW) + ty4*SW + x;
        unsigned long long vv[6][3];
        #pragma unroll
        for (int r=0;r<6;r++){
          #pragma unroll
          for (int d=0;d<3;d++){
            float v = base[r*SW + d];
            vv[r][d] = pack2(v,v);
          }
        }
        #pragma unroll
        for (int dy=0;dy<3;dy++){
          #pragma unroll
          for (int dx=0;dx<3;dx++){
            const float* wrow = &sw[(icl*9 + dy*3 + dx)*32 + oh*16];
            #pragma unroll
            for (int op=0; op<8; op++){
              unsigned long long wp = *(const unsigned long long*)(wrow + 2*op);
              ffma2(acc[0][op], vv[dy+0][dx], wp);
              ffma2(acc[1][op], vv[dy+1][dx], wp);
              ffma2(acc[2][op], vv[dy+2][dx], wp);
              ffma2(acc[3][op], vv[dy+3][dx], wp);
            }
          }
        }
      }
    } else {
      for (int dy=0; dy<3; dy++){
        #pragma unroll
        for (int dx=0; dx<3; dx++){
          #pragma unroll 2
          for (int icl=0; icl<CH; icl++){
            int ibase = icl*(SH*SW) + (dy*DIL)*SW + x + dx*DIL;
            float v0 = sin[ibase + (ty4+0)*SW];
            float v1 = sin[ibase + (ty4+1)*SW];
            float v2 = sin[ibase + (ty4+2)*SW];
            float v3 = sin[ibase + (ty4+3)*SW];
            unsigned long long vv0 = pack2(v0,v0);
            unsigned long long vv1 = pack2(v1,v1);
            unsigned long long vv2 = pack2(v2,v2);
            unsigned long long vv3 = pack2(v3,v3);
            const float* wrow = &sw[(icl*9 + dy*3 + dx)*32 + oh*16];
            #pragma unroll
            for (int op=0; op<8; op++){
              unsigned long long wp = *(const unsigned long long*)(wrow + 2*op);
              ffma2(acc[0][op], vv0, wp);
              ffma2(acc[1][op], vv1, wp);
              ffma2(acc[2][op], vv2, wp);
              ffma2(acc[3][op], vv3, wp);
            }
          }
        }
      }
    }
    __syncthreads();
  }

  const int xg = x0 + x;
  if (MODE==0 || MODE==1 || MODE==2){
    #pragma unroll
    for (int j=0;j<4;j++){
      int y = y0 + ty4 + j;
      #pragma unroll
      for (int op=0; op<8; op++){
        int oc = oh*16 + 2*op;
        float2 a = unpack2(acc[j][op]);
        float b0 = __ldg(bias+oc);
        float b1 = __ldg(bias+oc+1);
        int g0 = ((b*32+oc)*IMH + y)*IMW + xg;
        int g1 = g0 + HWSZ;
        if (MODE==0){
          g_z[g0] = sigmoidf_(a.x + b0);
          g_z[g1] = sigmoidf_(a.y + b1);
        } else if (MODE==1){
          g_rh[g0] = sigmoidf_(a.x + b0) * __ldg(hidden+g0);
          g_rh[g1] = sigmoidf_(a.y + b1) * __ldg(hidden+g1);
        } else {
          float q0 = tanhf(a.x + b0);
          float q1 = tanhf(a.y + b1);
          float z0 = g_z[g0], z1 = g_z[g1];
          float h0 = __ldg(hidden+g0), h1 = __ldg(hidden+g1);
          out[g0] = h0 + z0*(q0 - h0);
          out[g1] = h1 + z1*(q1 - h1);
        }
      }
    }
  } else if (MODE==3){
    float part[4];
    #pragma unroll
    for (int j=0;j<4;j++){
      float cv = 0.f;
      #pragma unroll
      for (int op=0; op<8; op++){
        int oc = oh*16 + 2*op;
        float2 a = unpack2(acc[j][op]);
        cv = fmaf(__ldg(aux+oc),   fmaxf(a.x,0.f), cv);
        cv = fmaf(__ldg(aux+oc+1), fmaxf(a.y,0.f), cv);
      }
      part[j] = cv;
    }
    if (oh==0){
      #pragma unroll
      for (int j=0;j<4;j++) s_red[(ty4+j)*32 + x] = part[j];
    }
    __syncthreads();
    if (oh==1){
      float cb = __ldg(aux2);
      #pragma unroll
      for (int j=0;j<4;j++){
        int y = y0+ty4+j;
        float cv = part[j] + s_red[(ty4+j)*32 + x] + cb;
        int pidx = (b*IMH + y)*IMW + xg;
        out [pidx] = cv;
        out2[pidx] = sigmoidf_(cv);
      }
    }
  } else { // MODE 4: relu(d1) -> g_d1
    #pragma unroll
    for (int j=0;j<4;j++){
      int y = y0+ty4+j;
      #pragma unroll
      for (int op=0; op<8; op++){
        int oc = oh*16 + 2*op;
        float2 a = unpack2(acc[j][op]);
        int g0 = ((b*32+oc)*IMH + y)*IMW + xg;
        g_d1[g0]        = fmaxf(a.x, 0.f);
        g_d1[g0+HWSZ]   = fmaxf(a.y, 0.f);
      }
    }
  }
}

// ---------------- dh2 + dh3 GEMM + softmax + argmax regression ------------
__global__ void __launch_bounds__(256) head_kernel(
    const float* __restrict__ db3,
    float* __restrict__ prob, float* __restrict__ nd)
{
  extern __shared__ float sm[];
  float* s_w3t = sm;             // 16384 : dh3^T [64][256]
  float* s_w2t = sm + 16384;     // 2048  : dh2^T [32][64]
  float* s_db3 = sm + 18432;     // 256
  float* s_d1  = sm + 18688;     // 2048  : d1 [32][64]
  float* s_d2  = sm + 20736;     // 4096  : d2 [64][64]
  float* s_l   = sm + 24832;     // 16640 : logits/e [256][65]
  float* s_inv = sm + 41472;     // 64

  const int tid  = threadIdx.x;
  const int lane = tid & 31;
  const int g    = tid >> 5;
  const int y    = blockIdx.x;
  const int b    = blockIdx.y;

  for (int i = tid; i < 16384; i += 256) s_w3t[i] = g_wt3[i];
  for (int i = tid; i < 2048;  i += 256) s_w2t[i] = g_wt2[i];
  if (tid < 256) s_db3[tid] = db3[tid];
  __syncthreads();

  for (int xt = 0; xt < 5; xt++){
    int x0 = xt*64;
    // stage d1 tile [32][64]
    for (int i = tid; i < 2048; i += 256){
      int ch = i >> 6, xp = i & 63;
      s_d1[i] = g_d1[((b*32+ch)*IMH + y)*IMW + x0 + xp];
    }
    __syncthreads();

    // d2 = relu(dh2 @ d1): thread -> px = tid&63, oc2 group (tid>>6)*16
    {
      int px  = tid & 63;
      int grp = tid >> 6;
      unsigned long long a2[8];
      #pragma unroll
      for (int k=0;k<8;k++) a2[k]=0ull;
      #pragma unroll 4
      for (int ic=0; ic<32; ic++){
        float v = s_d1[ic*64 + px];
        unsigned long long vv = pack2(v,v);
        const float* wr = &s_w2t[ic*64 + grp*16];
        #pragma unroll
        for (int k=0;k<8;k++){
          unsigned long long wp = *(const unsigned long long*)(wr + 2*k);
          ffma2(a2[k], vv, wp);
        }
      }
      #pragma unroll
      for (int k=0;k<8;k++){
        float2 a = unpack2(a2[k]);
        int oc2 = grp*16 + 2*k;
        s_d2[oc2*64 + px]     = fmaxf(a.x, 0.f);
        s_d2[(oc2+1)*64 + px] = fmaxf(a.y, 0.f);
      }
    }
    __syncthreads();

    // logits: warp g -> oc [g*32, g*32+32), px lane & lane+32 (f32x2 pairs)
    {
      unsigned long long a0[16], a1[16];
      #pragma unroll
      for (int k=0;k<16;k++){ a0[k]=0ull; a1[k]=0ull; }
      int x1 = lane, x2 = lane+32;
      #pragma unroll 4
      for (int ic=0; ic<64; ic++){
        float v0 = s_d2[ic*64 + x1];
        float v1 = s_d2[ic*64 + x2];
        unsigned long long vv0 = pack2(v0,v0);
        unsigned long long vv1 = pack2(v1,v1);
        const float* wr = &s_w3t[ic*256 + g*32];
        #pragma unroll
        for (int k=0;k<16;k++){
          unsigned long long wp = *(const unsigned long long*)(wr + 2*k);
          ffma2(a0[k], vv0, wp);
          ffma2(a1[k], vv1, wp);
        }
      }
      #pragma unroll
      for (int k=0;k<16;k++){
        int oc = g*32 + 2*k;
        float2 p0 = unpack2(a0[k]);
        float2 p1 = unpack2(a1[k]);
        float ba = s_db3[oc], bb = s_db3[oc+1];
        s_l[oc*65 + x1]     = p0.x + ba;
        s_l[(oc+1)*65 + x1] = p0.y + bb;
        s_l[oc*65 + x2]     = p1.x + ba;
        s_l[(oc+1)*65 + x2] = p1.y + bb;
      }
    }
    __syncthreads();

    // softmax + argmax window; warp g handles pixels [g*8, g*8+8)
    for (int p8 = 0; p8 < 8; p8++){
      int px = g*8 + p8;
      float lv[8];
      float m = -INFINITY; int mi = 0;
      #pragma unroll
      for (int k=0;k<8;k++){
        int oc = lane + k*32;
        lv[k] = s_l[oc*65 + px];
        if (lv[k] > m){ m = lv[k]; mi = oc; }
      }
      #pragma unroll
      for (int off=16; off; off>>=1){
        float om = __shfl_xor_sync(0xffffffffu, m,  off);
        int   oi = __shfl_xor_sync(0xffffffffu, mi, off);
        if (om > m || (om == m && oi < mi)){ m = om; mi = oi; }
      }
      float ssum = 0.f;
      #pragma unroll
      for (int k=0;k<8;k++){
        float e = __expf(lv[k] - m);
        s_l[(lane + k*32)*65 + px] = e;
        ssum += e;
      }
      #pragma unroll
      for (int off=16; off; off>>=1) ssum += __shfl_xor_sync(0xffffffffu, ssum, off);
      float inv = 1.f/ssum;
      __syncwarp();
      float aa = 0.f, bb = 0.f;
      if (lane < 9){
        int ocw = mi - 4 + lane;
        ocw = max(0, min(255, ocw));
        float pw = s_l[ocw*65 + px] * inv;
        aa = (float)ocw * pw;
        bb = pw;
      }
      #pragma unroll
      for (int off=16; off; off>>=1){
        aa += __shfl_xor_sync(0xffffffffu, aa, off);
        bb += __shfl_xor_sync(0xffffffffu, bb, off);
      }
      if (lane == 0){
        s_inv[px] = inv;
        nd[(b*IMH + y)*IMW + x0 + px] = (aa/(1e-6f + bb)) * (1.f/255.f);
      }
    }
    __syncthreads();

    // coalesced prob writeout
    for (int i = tid; i < 16384; i += 256){
      int oc = i >> 6, xp = i & 63;
      prob[((b*256+oc)*IMH + y)*IMW + x0 + xp] = s_l[oc*65 + xp] * s_inv[xp];
    }
    __syncthreads();
  }
}

// ---------------- launch ---------------------------------------------------
extern "C" void kernel_launch(void* const* d_in, const int* in_sizes, int n_in,
                              void* d_out, int out_size)
{
  const float* hidden = (const float*)d_in[0];
  const float* depth  = (const float*)d_in[1];
  const float* corr   = (const float*)d_in[2];
  const float* Wz  = (const float*)d_in[3];
  const float* bz  = (const float*)d_in[4];
  const float* Wr  = (const float*)d_in[5];
  const float* br  = (const float*)d_in[6];
  const float* Wq  = (const float*)d_in[7];
  const float* bq  = (const float*)d_in[8];
  const float* dh1 = (const float*)d_in[9];
  const float* dh2 = (const float*)d_in[10];
  const float* dh3 = (const float*)d_in[11];
  const float* db3 = (const float*)d_in[12];
  const float* ch1 = (const float*)d_in[13];
  const float* ch2 = (const float*)d_in[14];
  const float* cb2 = (const float*)d_in[15];

  float* out      = (float*)d_out;
  float* h_out    = out;
  float* nd_out   = h_out   + (size_t)BB*32*HWSZ;
  float* prob_out = nd_out  + (size_t)BB*HWSZ;
  float* conf_out = prob_out+ (size_t)BB*256*HWSZ;
  float* c0_out   = conf_out+ (size_t)BB*HWSZ;

  // dynamic smem sizes (set unconditionally — no static state allowed)
  const int SM_GRU  = (2*(8*18*34) + 2*(8*288)) * 4;            // 57600
  const int SM_HEADC= (2*(8*20*36) + 2*(8*288) + 512) * 4;      // 66560
  cudaFuncSetAttribute(conv_pipe<0>, cudaFuncAttributeMaxDynamicSharedMemorySize, SM_GRU);
  cudaFuncSetAttribute(conv_pipe<1>, cudaFuncAttributeMaxDynamicSharedMemorySize, SM_GRU);
  cudaFuncSetAttribute(conv_pipe<2>, cudaFuncAttributeMaxDynamicSharedMemorySize, SM_GRU);
  cudaFuncSetAttribute(conv_pipe<3>, cudaFuncAttributeMaxDynamicSharedMemorySize, SM_HEADC);
  cudaFuncSetAttribute(conv_pipe<4>, cudaFuncAttributeMaxDynamicSharedMemorySize, SM_HEADC);
  cudaFuncSetAttribute(head_kernel,  cudaFuncAttributeMaxDynamicSharedMemorySize, 41536*4);

  dim3 tg(182, 7);
  wtrans_kernel<<<tg, 256>>>(Wz, Wr, Wq, dh1, ch1, dh2, dh3);

  dim3 cg(IMW/32, IMH/16, BB);
  conv_pipe<0><<<cg,256,SM_GRU>>>(hidden, depth, corr, bz, hidden, nullptr, nullptr, nullptr, nullptr);
  conv_pipe<1><<<cg,256,SM_GRU>>>(hidden, depth, corr, br, hidden, nullptr, nullptr, nullptr, nullptr);
  conv_pipe<2><<<cg,256,SM_GRU>>>(hidden, depth, corr, bq, hidden, nullptr, nullptr, h_out, nullptr);
  conv_pipe<3><<<cg,256,SM_HEADC>>>(h_out, nullptr, nullptr, nullptr, nullptr, ch2, cb2, c0_out, conf_out);
  conv_pipe<4><<<cg,256,SM_HEADC>>>(h_out, nullptr, nullptr, nullptr, nullptr, nullptr, nullptr, nullptr, nullptr);

  head_kernel<<<dim3(IMH, BB), 256, 41536*4>>>(db3, prob_out, nd_out);
}

// round 9
// speedup vs baseline: 1.5048x; 1.5048x over previous
#include <cuda_runtime.h>
#include <cuda_bf16.h>
#include <math.h>
#include <stdint.h>

#define IMH 256
#define IMW 320
#define HWSZ (IMH*IMW)
#define BB 4
#define NCT 161
#define NCHUNK 21

// ---------------- scratch (device globals; no allocation allowed) ----------
__device__ float g_z [BB*32*HWSZ];
__device__ float g_rh[BB*32*HWSZ];
__device__ float g_d1[BB*32*HWSZ];
__device__ float g_wtd[32*9*32];
__device__ float g_wtc[32*9*32];
__device__ float g_wt2[32*64];    // dh2^T  [ic][oc2]
__device__ float g_wt3[64*256];   // dh3^T  [ic][oc]
// GRU weights as mma B-fragments: [conv][chunk][ver(hi/lo)][s][nb][lane][2 words]
__device__ uint32_t g_wf[3*NCHUNK*2560];

__device__ __forceinline__ float sigmoidf_(float v){ return 1.f/(1.f+__expf(-v)); }

// ---- packed fp32x2 helpers ------------------------------------------------
__device__ __forceinline__ unsigned long long pack2(float a, float b){
  unsigned long long r; asm("mov.b64 %0,{%1,%2};":"=l"(r):"f"(a),"f"(b)); return r;
}
__device__ __forceinline__ void ffma2(unsigned long long& d, unsigned long long a, unsigned long long b){
  asm("fma.rn.f32x2 %0, %1, %2, %0;":"+l"(d):"l"(a),"l"(b));
}
__device__ __forceinline__ float2 unpack2(unsigned long long v){
  float2 r; asm("mov.b64 {%0,%1}, %2;":"=f"(r.x),"=f"(r.y):"l"(v)); return r;
}

// ---- cp.async helpers -----------------------------------------------------
__device__ __forceinline__ void cp_async4(float* smem_dst, const float* gsrc, bool valid){
  unsigned int d = (unsigned int)__cvta_generic_to_shared(smem_dst);
  int sz = valid ? 4 : 0;
  asm volatile("cp.async.ca.shared.global [%0], [%1], 4, %2;\n" :: "r"(d), "l"(gsrc), "r"(sz));
}
__device__ __forceinline__ void cp_async16(void* smem_dst, const void* gsrc){
  unsigned int d = (unsigned int)__cvta_generic_to_shared(smem_dst);
  asm volatile("cp.async.cg.shared.global [%0], [%1], 16;\n" :: "r"(d), "l"(gsrc));
}
__device__ __forceinline__ void cp_commit(){ asm volatile("cp.async.commit_group;\n"); }
template<int N> __device__ __forceinline__ void cp_wait(){ asm volatile("cp.async.wait_group %0;\n"::"n"(N)); }

// ---- bf16 pack: lower 16 bits = bf16(lo_elem), upper = bf16(hi_elem) ------
__device__ __forceinline__ uint32_t packbf(float lo_elem, float hi_elem){
  uint32_t r; asm("cvt.rn.bf16x2.f32 %0, %1, %2;" : "=r"(r) : "f"(hi_elem), "f"(lo_elem)); return r;
}

// ---- warp mma m16n8k16 bf16 (sm_80+ baseline PTX; compiles on compute_103)
__device__ __forceinline__ void mma_bf16(float& d0,float& d1,float& d2,float& d3,
    uint32_t a0,uint32_t a1,uint32_t a2,uint32_t a3, uint32_t b0,uint32_t b1){
  asm volatile("mma.sync.aligned.m16n8k16.row.col.f32.bf16.bf16.f32 "
    "{%0,%1,%2,%3}, {%4,%5,%6,%7}, {%8,%9}, {%0,%1,%2,%3};"
    : "+f"(d0),"+f"(d1),"+f"(d2),"+f"(d3)
    : "r"(a0),"r"(a1),"r"(a2),"r"(a3),"r"(b0),"r"(b1));
}

// ---------------- weight transforms (head path) ----------------------------
__global__ void wtrans_kernel(const float* __restrict__ dh1, const float* __restrict__ ch1,
                              const float* __restrict__ dh2, const float* __restrict__ dh3){
  int t = blockIdx.y;
  int idx = blockIdx.x*256 + threadIdx.x;
  if (t==0 || t==1){
    const float* src = (t==0)?dh1:ch1;
    float* dst = (t==0)?g_wtd:g_wtc;
    if (idx < 32*288){
      int ic = idx/288; int r = idx - ic*288; int tap = r>>5; int oc = r&31;
      dst[idx] = src[(oc*32+ic)*9+tap];
    }
  } else if (t==2){
    if (idx < 2048) g_wt2[idx] = dh2[(idx&63)*32 + (idx>>6)];
  } else {
    if (idx < 16384) g_wt3[idx] = dh3[(idx&255)*64 + (idx>>8)];
  }
}

// ---------------- GRU weights -> hi/lo bf16 B-fragments --------------------
__global__ void wtrans_frag(const float* __restrict__ Wz, const float* __restrict__ Wr,
                            const float* __restrict__ Wq){
  int idx = blockIdx.x*256 + threadIdx.x;   // 3 * 21 * 1280
  if (idx >= 3*NCHUNK*1280) return;
  int t3 = idx / (NCHUNK*1280);
  int r  = idx % (NCHUNK*1280);
  int cc = r / 1280; r %= 1280;
  int ver= r / 640;  r %= 640;
  int s  = r / 128;  r %= 128;
  int nb = r / 32;
  int lane = r % 32;
  int g = lane>>2, tt = lane&3;
  int oc = nb*8 + g;
  const float* W = (t3==0)?Wz:((t3==1)?Wr:Wq);
  auto wval = [&](int k)->float{
    if (k >= 72) return 0.f;
    int ic = cc*8 + k/9;
    if (ic >= NCT) return 0.f;
    return W[(oc*NCT+ic)*9 + (k%9)];
  };
  int k0 = s*16 + 2*tt;
  float w00 = wval(k0),   w01 = wval(k0+1);
  float w10 = wval(k0+8), w11 = wval(k0+9);
  uint32_t b0, b1;
  if (ver == 0){
    b0 = packbf(w00, w01);
    b1 = packbf(w10, w11);
  } else {
    float h00 = __bfloat162float(__float2bfloat16(w00));
    float h01 = __bfloat162float(__float2bfloat16(w01));
    float h10 = __bfloat162float(__float2bfloat16(w10));
    float h11 = __bfloat162float(__float2bfloat16(w11));
    b0 = packbf(w00-h00, w01-h01);
    b1 = packbf(w10-h10, w11-h11);
  }
  uint32_t* dst = g_wf + ((size_t)t3*NCHUNK + cc)*2560
                       + (((ver*5+s)*4+nb)*32 + lane)*2;
  dst[0] = b0; dst[1] = b1;
}

// ============= GRU conv via warp-mma bf16 (hi/lo split) ===================
// MODE 0: z ; MODE 1: rh ; MODE 2: q -> h
// CTA 128 thr / 4 warps; tile 32x4 px (warp w = tile row w), 32 oc.
// K = 21 chunks x 80 (8 ic x 9 taps padded). D = 32 f32 regs/thread.
template<int MODE>
__global__ void __launch_bounds__(128,4) gru_hmma(
    const float* __restrict__ in_h, const float* __restrict__ depth,
    const float* __restrict__ corr, const float* __restrict__ bias,
    const float* __restrict__ hidden, float* __restrict__ out)
{
  extern __shared__ __align__(16) unsigned char smx[];
  uint32_t* s_wf = (uint32_t*)smx;            // 2 x 2560 words = 20480 B
  float*    s_raw= (float*)(smx + 20480);     // 2 x 1632 f     = 13056 B

  const int tid  = threadIdx.x;
  const int wrp  = tid >> 5;
  const int lane = tid & 31;
  const int g    = lane >> 2;
  const int t    = lane & 3;
  const int x0 = blockIdx.x*32, y0 = blockIdx.y*4, b = blockIdx.z;

  const float* i0 = (MODE==2) ? (const float*)g_rh : in_h;
  const uint32_t* wsrc = g_wf + (size_t)MODE*NCHUNK*2560;

  // per-thread im2col offsets: k = 16s + 2t + (j&1) + (j>>1)*8
  int offA[5][4];
  #pragma unroll
  for (int s=0;s<5;s++){
    #pragma unroll
    for (int j=0;j<4;j++){
      int k = s*16 + 2*t + (j&1) + (j>>1)*8;
      offA[s][j] = (k<72) ? ((k/9)*204 + ((k%9)/3)*34 + (k%9)%3) : 0;
    }
  }

  auto prefetch = [&](int cc, int buf){
    float* din = s_raw + buf*1632;
    for (int idx = tid; idx < 1632; idx += 128){
      int icl = idx/204;
      int rem = idx - icl*204;
      int sy  = rem/34;
      int sx  = rem - sy*34;
      int c   = cc*8 + icl;
      int gy  = y0 + sy - 1;
      int gx  = x0 + sx - 1;
      bool ok = (c < NCT) && ((unsigned)gy < IMH) && ((unsigned)gx < IMW);
      int cs  = ok ? c : 0;
      const float* p;
      if (cs < 32)       p = i0    + (size_t)(b*32 + cs)*HWSZ;
      else if (cs == 32) p = depth + (size_t)b*HWSZ;
      else               p = corr  + (size_t)(b*128 + (cs-33))*HWSZ;
      int off = ok ? (gy*IMW + gx) : 0;
      cp_async4(din + idx, p + off, ok);
    }
    const uint4* gsrc = (const uint4*)(wsrc + (size_t)cc*2560);
    uint4* dst = (uint4*)(s_wf + buf*2560);
    for (int i = tid; i < 640; i += 128)
      cp_async16(dst + i, gsrc + i);
  };

  float D[32];
  #pragma unroll
  for (int i=0;i<32;i++) D[i]=0.f;

  prefetch(0, 0); cp_commit();

  for (int cc = 0; cc < NCHUNK; cc++){
    cp_wait<0>();
    __syncthreads();
    if (cc+1 < NCHUNK){ prefetch(cc+1, (cc+1)&1); cp_commit(); }

    const float* raw = s_raw + (cc&1)*1632 + wrp*34;
    const uint32_t* wf = s_wf + (cc&1)*2560;

    #pragma unroll
    for (int s=0;s<5;s++){
      #pragma unroll
      for (int mb=0;mb<2;mb++){
        const float* pA = raw + mb*16 + g;
        const float* pB = pA + 8;
        float vA0 = pA[offA[s][0]], vA1 = pA[offA[s][1]];
        float vB0 = pB[offA[s][0]], vB1 = pB[offA[s][1]];
        uint32_t ah0 = packbf(vA0, vA1);
        uint32_t ah1 = packbf(vB0, vB1);
        float hA0 = __uint_as_float(ah0<<16), hA1 = __uint_as_float(ah0 & 0xffff0000u);
        float hB0 = __uint_as_float(ah1<<16), hB1 = __uint_as_float(ah1 & 0xffff0000u);
        uint32_t al0 = packbf(vA0-hA0, vA1-hA1);
        uint32_t al1 = packbf(vB0-hB0, vB1-hB1);
        uint32_t ah2=0, ah3=0, al2=0, al3=0;
        if (s < 4){
          float wA0 = pA[offA[s][2]], wA1 = pA[offA[s][3]];
          float wB0 = pB[offA[s][2]], wB1 = pB[offA[s][3]];
          ah2 = packbf(wA0, wA1);
          ah3 = packbf(wB0, wB1);
          float qA0 = __uint_as_float(ah2<<16), qA1 = __uint_as_float(ah2 & 0xffff0000u);
          float qB0 = __uint_as_float(ah3<<16), qB1 = __uint_as_float(ah3 & 0xffff0000u);
          al2 = packbf(wA0-qA0, wA1-qA1);
          al3 = packbf(wB0-qB0, wB1-qB1);
        }
        #pragma unroll
        for (int nb=0;nb<4;nb++){
          uint2 bh = *(const uint2*)(wf + (s*4+nb)*64 + lane*2);
          uint2 bl = *(const uint2*)(wf + 1280 + (s*4+nb)*64 + lane*2);
          float* dd = &D[(mb*4+nb)*4];
          mma_bf16(dd[0],dd[1],dd[2],dd[3], ah0,ah1,ah2,ah3, bh.x,bh.y);
          mma_bf16(dd[0],dd[1],dd[2],dd[3], ah0,ah1,ah2,ah3, bl.x,bl.y);
          mma_bf16(dd[0],dd[1],dd[2],dd[3], al0,al1,al2,al3, bh.x,bh.y);
        }
      }
    }
  }

  // epilogue: warp w = row y0+w. D frag (m16n8): d0:(g,2t) d1:(g,2t+1) d2:(g+8,2t) d3:(g+8,2t+1)
  {
    const int y = y0 + wrp;
    auto emit = [&](int oc, int x, float v){
      int gi = ((b*32+oc)*IMH + y)*IMW + x;
      float r = v + __ldg(bias+oc);
      if (MODE==0){
        g_z[gi] = sigmoidf_(r);
      } else if (MODE==1){
        g_rh[gi] = sigmoidf_(r) * __ldg(hidden+gi);
      } else {
        float q  = tanhf(r);
        float z  = g_z[gi];
        float h0 = __ldg(hidden+gi);
        out[gi] = h0 + z*(q - h0);
      }
    };
    #pragma unroll
    for (int mb=0;mb<2;mb++){
      int xA = x0 + mb*16 + g;
      #pragma unroll
      for (int nb=0;nb<4;nb++){
        float* dd = &D[(mb*4+nb)*4];
        int oc0 = nb*8 + 2*t;
        emit(oc0,   xA,   dd[0]);
        emit(oc0+1, xA,   dd[1]);
        emit(oc0,   xA+8, dd[2]);
        emit(oc0+1, xA+8, dd[3]);
      }
    }
  }
}

// ============= head convs (Cin=32, dil=2) — f32x2 pipelined (R4) ==========
template<int MODE>
__global__ void __launch_bounds__(256,2) conv_pipe(
    const float* __restrict__ in_h,
    const float* __restrict__ aux, const float* __restrict__ aux2,
    float* __restrict__ out, float* __restrict__ out2)
{
  constexpr int DIL = 2;
  constexpr int SH  = 20;
  constexpr int SW  = 36;
  constexpr int CH  = 8;
  constexpr int TILE = CH*SH*SW;
  constexpr int WCH  = CH*288;
  constexpr int NC   = 4;

  extern __shared__ float sm[];
  float* s_in  = sm;
  float* s_w   = sm + 2*TILE;
  float* s_red = s_w + 2*WCH;

  const int tid = threadIdx.x;
  const int x   = tid & 31;
  const int ty  = (tid >> 5) & 3;
  const int oh  = tid >> 7;
  const int ty4 = ty*4;
  const int x0  = blockIdx.x*32;
  const int y0  = blockIdx.y*16;
  const int b   = blockIdx.z;

  const float* WtT = (MODE==3) ? g_wtc : g_wtd;

  auto prefetch = [&](int cc, int buf){
    int c0 = cc*CH;
    float* din = s_in + buf*TILE;
    float* dw  = s_w  + buf*WCH;
    for (int idx = tid; idx < TILE; idx += 256){
      int icl = idx/(SH*SW);
      int rem = idx - icl*(SH*SW);
      int sy  = rem/SW;
      int sx  = rem - sy*SW;
      int c   = c0+icl;
      int gy  = y0 + sy - DIL;
      int gx  = x0 + sx - DIL;
      bool ok = ((unsigned)gy < IMH) && ((unsigned)gx < IMW);
      const float* p = in_h + (size_t)(b*32 + c)*HWSZ;
      int off = ok ? (gy*IMW + gx) : 0;
      cp_async4(din + idx, p + off, ok);
    }
    int wbase = c0*288;
    for (int idx = tid; idx < WCH; idx += 256)
      cp_async4(dw + idx, WtT + wbase + idx, true);
  };

  unsigned long long acc[4][8];
  #pragma unroll
  for (int j=0;j<4;j++)
    #pragma unroll
    for (int o=0;o<8;o++) acc[j][o] = 0ull;

  prefetch(0, 0); cp_commit();

  for (int cc=0; cc<NC; cc++){
    if (cc+1 < NC){ prefetch(cc+1, (cc+1)&1); cp_commit(); cp_wait<1>(); }
    else          { cp_wait<0>(); }
    __syncthreads();

    const float* sin = s_in + (cc&1)*TILE;
    const float* sw  = s_w  + (cc&1)*WCH;

    for (int dy=0; dy<3; dy++){
      #pragma unroll
      for (int dx=0; dx<3; dx++){
        #pragma unroll 2
        for (int icl=0; icl<CH; icl++){
          int ibase = icl*(SH*SW) + (dy*DIL)*SW + x + dx*DIL;
          float v0 = sin[ibase + (ty4+0)*SW];
          float v1 = sin[ibase + (ty4+1)*SW];
          float v2 = sin[ibase + (ty4+2)*SW];
          float v3 = sin[ibase + (ty4+3)*SW];
          unsigned long long vv0 = pack2(v0,v0);
          unsigned long long vv1 = pack2(v1,v1);
          unsigned long long vv2 = pack2(v2,v2);
          unsigned long long vv3 = pack2(v3,v3);
          const float* wrow = &sw[(icl*9 + dy*3 + dx)*32 + oh*16];
          #pragma unroll
          for (int op=0; op<8; op++){
            unsigned long long wp = *(const unsigned long long*)(wrow + 2*op);
            ffma2(acc[0][op], vv0, wp);
            ffma2(acc[1][op], vv1, wp);
            ffma2(acc[2][op], vv2, wp);
            ffma2(acc[3][op], vv3, wp);
          }
        }
      }
    }
    __syncthreads();
  }

  const int xg = x0 + x;
  if (MODE==3){
    float part[4];
    #pragma unroll
    for (int j=0;j<4;j++){
      float cv = 0.f;
      #pragma unroll
      for (int op=0; op<8; op++){
        int oc = oh*16 + 2*op;
        float2 a = unpack2(acc[j][op]);
        cv = fmaf(__ldg(aux+oc),   fmaxf(a.x,0.f), cv);
        cv = fmaf(__ldg(aux+oc+1), fmaxf(a.y,0.f), cv);
      }
      part[j] = cv;
    }
    if (oh==0){
      #pragma unroll
      for (int j=0;j<4;j++) s_red[(ty4+j)*32 + x] = part[j];
    }
    __syncthreads();
    if (oh==1){
      float cb = __ldg(aux2);
      #pragma unroll
      for (int j=0;j<4;j++){
        int y = y0+ty4+j;
        float cv = part[j] + s_red[(ty4+j)*32 + x] + cb;
        int pidx = (b*IMH + y)*IMW + xg;
        out [pidx] = cv;
        out2[pidx] = sigmoidf_(cv);
      }
    }
  } else {
    #pragma unroll
    for (int j=0;j<4;j++){
      int y = y0+ty4+j;
      #pragma unroll
      for (int op=0; op<8; op++){
        int oc = oh*16 + 2*op;
        float2 a = unpack2(acc[j][op]);
        int g0 = ((b*32+oc)*IMH + y)*IMW + xg;
        g_d1[g0]      = fmaxf(a.x, 0.f);
        g_d1[g0+HWSZ] = fmaxf(a.y, 0.f);
      }
    }
  }
}

// ---------------- dh2 + dh3 GEMM + softmax + argmax regression ------------
__global__ void __launch_bounds__(256) head_kernel(
    const float* __restrict__ db3,
    float* __restrict__ prob, float* __restrict__ nd)
{
  extern __shared__ float sm[];
  float* s_w3t = sm;             // 16384 : dh3^T [64][256]
  float* s_w2t = sm + 16384;     // 2048
  float* s_db3 = sm + 18432;     // 256
  float* s_d1  = sm + 18688;     // 2048
  float* s_d2  = sm + 20736;     // 4096
  float* s_l   = sm + 24832;     // 16640
  float* s_inv = sm + 41472;     // 64

  const int tid  = threadIdx.x;
  const int lane = tid & 31;
  const int g    = tid >> 5;
  const int y    = blockIdx.x;
  const int b    = blockIdx.y;

  for (int i = tid; i < 16384; i += 256) s_w3t[i] = g_wt3[i];
  for (int i = tid; i < 2048;  i += 256) s_w2t[i] = g_wt2[i];
  if (tid < 256) s_db3[tid] = db3[tid];
  __syncthreads();

  for (int xt = 0; xt < 5; xt++){
    int x0 = xt*64;
    for (int i = tid; i < 2048; i += 256){
      int ch = i >> 6, xp = i & 63;
      s_d1[i] = g_d1[((b*32+ch)*IMH + y)*IMW + x0 + xp];
    }
    __syncthreads();

    {
      int px  = tid & 63;
      int grp = tid >> 6;
      unsigned long long a2[8];
      #pragma unroll
      for (int k=0;k<8;k++) a2[k]=0ull;
      #pragma unroll 4
      for (int ic=0; ic<32; ic++){
        float v = s_d1[ic*64 + px];
        unsigned long long vv = pack2(v,v);
        const float* wr = &s_w2t[ic*64 + grp*16];
        #pragma unroll
        for (int k=0;k<8;k++){
          unsigned long long wp = *(const unsigned long long*)(wr + 2*k);
          ffma2(a2[k], vv, wp);
        }
      }
      #pragma unroll
      for (int k=0;k<8;k++){
        float2 a = unpack2(a2[k]);
        int oc2 = grp*16 + 2*k;
        s_d2[oc2*64 + px]     = fmaxf(a.x, 0.f);
        s_d2[(oc2+1)*64 + px] = fmaxf(a.y, 0.f);
      }
    }
    __syncthreads();

    {
      unsigned long long a0[16], a1[16];
      #pragma unroll
      for (int k=0;k<16;k++){ a0[k]=0ull; a1[k]=0ull; }
      int x1 = lane, x2 = lane+32;
      #pragma unroll 4
      for (int ic=0; ic<64; ic++){
        float v0 = s_d2[ic*64 + x1];
        float v1 = s_d2[ic*64 + x2];
        unsigned long long vv0 = pack2(v0,v0);
        unsigned long long vv1 = pack2(v1,v1);
        const float* wr = &s_w3t[ic*256 + g*32];
        #pragma unroll
        for (int k=0;k<16;k++){
          unsigned long long wp = *(const unsigned long long*)(wr + 2*k);
          ffma2(a0[k], vv0, wp);
          ffma2(a1[k], vv1, wp);
        }
      }
      #pragma unroll
      for (int k=0;k<16;k++){
        int oc = g*32 + 2*k;
        float2 p0 = unpack2(a0[k]);
        float2 p1 = unpack2(a1[k]);
        float ba = s_db3[oc], bb = s_db3[oc+1];
        s_l[oc*65 + x1]     = p0.x + ba;
        s_l[(oc+1)*65 + x1] = p0.y + bb;
        s_l[oc*65 + x2]     = p1.x + ba;
        s_l[(oc+1)*65 + x2] = p1.y + bb;
      }
    }
    __syncthreads();

    for (int p8 = 0; p8 < 8; p8++){
      int px = g*8 + p8;
      float lv[8];
      float m = -INFINITY; int mi = 0;
      #pragma unroll
      for (int k=0;k<8;k++){
        int oc = lane + k*32;
        lv[k] = s_l[oc*65 + px];
        if (lv[k] > m){ m = lv[k]; mi = oc; }
      }
      #pragma unroll
      for (int off=16; off; off>>=1){
        float om = __shfl_xor_sync(0xffffffffu, m,  off);
        int   oi = __shfl_xor_sync(0xffffffffu, mi, off);
        if (om > m || (om == m && oi < mi)){ m = om; mi = oi; }
      }
      float ssum = 0.f;
      #pragma unroll
      for (int k=0;k<8;k++){
        float e = __expf(lv[k] - m);
        s_l[(lane + k*32)*65 + px] = e;
        ssum += e;
      }
      #pragma unroll
      for (int off=16; off; off>>=1) ssum += __shfl_xor_sync(0xffffffffu, ssum, off);
      float inv = 1.f/ssum;
      __syncwarp();
      float aa = 0.f, bb = 0.f;
      if (lane < 9){
        int ocw = mi - 4 + lane;
        ocw = max(0, min(255, ocw));
        float pw = s_l[ocw*65 + px] * inv;
        aa = (float)ocw * pw;
        bb = pw;
      }
      #pragma unroll
      for (int off=16; off; off>>=1){
        aa += __shfl_xor_sync(0xffffffffu, aa, off);
        bb += __shfl_xor_sync(0xffffffffu, bb, off);
      }
      if (lane == 0){
        s_inv[px] = inv;
        nd[(b*IMH + y)*IMW + x0 + px] = (aa/(1e-6f + bb)) * (1.f/255.f);
      }
    }
    __syncthreads();

    for (int i = tid; i < 16384; i += 256){
      int oc = i >> 6, xp = i & 63;
      prob[((b*256+oc)*IMH + y)*IMW + x0 + xp] = s_l[oc*65 + xp] * s_inv[xp];
    }
    __syncthreads();
  }
}

// ---------------- launch ---------------------------------------------------
extern "C" void kernel_launch(void* const* d_in, const int* in_sizes, int n_in,
                              void* d_out, int out_size)
{
  const float* hidden = (const float*)d_in[0];
  const float* depth  = (const float*)d_in[1];
  const float* corr   = (const float*)d_in[2];
  const float* Wz  = (const float*)d_in[3];
  const float* bz  = (const float*)d_in[4];
  const float* Wr  = (const float*)d_in[5];
  const float* br  = (const float*)d_in[6];
  const float* Wq  = (const float*)d_in[7];
  const float* bq  = (const float*)d_in[8];
  const float* dh1 = (const float*)d_in[9];
  const float* dh2 = (const float*)d_in[10];
  const float* dh3 = (const float*)d_in[11];
  const float* db3 = (const float*)d_in[12];
  const float* ch1 = (const float*)d_in[13];
  const float* ch2 = (const float*)d_in[14];
  const float* cb2 = (const float*)d_in[15];

  float* out      = (float*)d_out;
  float* h_out    = out;
  float* nd_out   = h_out   + (size_t)BB*32*HWSZ;
  float* prob_out = nd_out  + (size_t)BB*HWSZ;
  float* conf_out = prob_out+ (size_t)BB*256*HWSZ;
  float* c0_out   = conf_out+ (size_t)BB*HWSZ;

  const int SM_HMMA = 20480 + 13056;                           // 33536
  const int SM_HEADC= (2*(8*20*36) + 2*(8*288) + 512) * 4;     // 66560
  cudaFuncSetAttribute(gru_hmma<0>, cudaFuncAttributeMaxDynamicSharedMemorySize, SM_HMMA);
  cudaFuncSetAttribute(gru_hmma<1>, cudaFuncAttributeMaxDynamicSharedMemorySize, SM_HMMA);
  cudaFuncSetAttribute(gru_hmma<2>, cudaFuncAttributeMaxDynamicSharedMemorySize, SM_HMMA);
  cudaFuncSetAttribute(conv_pipe<3>, cudaFuncAttributeMaxDynamicSharedMemorySize, SM_HEADC);
  cudaFuncSetAttribute(conv_pipe<4>, cudaFuncAttributeMaxDynamicSharedMemorySize, SM_HEADC);
  cudaFuncSetAttribute(head_kernel,  cudaFuncAttributeMaxDynamicSharedMemorySize, 41536*4);

  wtrans_kernel<<<dim3(64,4), 256>>>(dh1, ch1, dh2, dh3);
  wtrans_frag<<<(3*NCHUNK*1280 + 255)/256, 256>>>(Wz, Wr, Wq);

  dim3 gg(IMW/32, IMH/4, BB);
  gru_hmma<0><<<gg,128,SM_HMMA>>>(hidden, depth, corr, bz, hidden, nullptr);
  gru_hmma<1><<<gg,128,SM_HMMA>>>(hidden, depth, corr, br, hidden, nullptr);
  gru_hmma<2><<<gg,128,SM_HMMA>>>(hidden, depth, corr, bq, hidden, h_out);

  dim3 cg(IMW/32, IMH/16, BB);
  conv_pipe<3><<<cg,256,SM_HEADC>>>(h_out, ch2, cb2, c0_out, conf_out);
  conv_pipe<4><<<cg,256,SM_HEADC>>>(h_out, nullptr, nullptr, nullptr, nullptr);

  head_kernel<<<dim3(IMH, BB), 256, 41536*4>>>(db3, prob_out, nd_out);
}

// round 12
// speedup vs baseline: 1.6547x; 1.0996x over previous
#include <cuda_runtime.h>
#include <cuda_bf16.h>
#include <math.h>
#include <stdint.h>

#define IMH 256
#define IMW 320
#define HWSZ (IMH*IMW)
#define BB 4
#define NCT 161
#define NCHUNK 21

// frag table offsets (32-bit words)
#define QOFF 107520          // 21*5120

// ---------------- scratch (device globals; no allocation allowed) ----------
__device__ float g_z [BB*32*HWSZ];
__device__ float g_rh[BB*32*HWSZ];
__device__ float g_d1[BB*32*HWSZ];
__device__ float g_wtd[32*9*32];
__device__ float g_wtc[32*9*32];
__device__ float g_wt2[32*64];    // dh2^T  [ic][oc2]
__device__ float g_wt3[64*256];   // dh3^T  [ic][oc]
// B fragments: zr [21][2][5][8][32][2] | q [21][2][5][4][32][2]
__device__ uint32_t g_wf[161280];

__device__ __forceinline__ float sigmoidf_(float v){ return 1.f/(1.f+__expf(-v)); }

// ---- packed fp32x2 helpers ------------------------------------------------
__device__ __forceinline__ unsigned long long pack2(float a, float b){
  unsigned long long r; asm("mov.b64 %0,{%1,%2};":"=l"(r):"f"(a),"f"(b)); return r;
}
__device__ __forceinline__ void ffma2(unsigned long long& d, unsigned long long a, unsigned long long b){
  asm("fma.rn.f32x2 %0, %1, %2, %0;":"+l"(d):"l"(a),"l"(b));
}
__device__ __forceinline__ float2 unpack2(unsigned long long v){
  float2 r; asm("mov.b64 {%0,%1}, %2;":"=f"(r.x),"=f"(r.y):"l"(v)); return r;
}

// ---- cp.async helpers -----------------------------------------------------
__device__ __forceinline__ void cp_async4(float* smem_dst, const float* gsrc, bool valid){
  unsigned int d = (unsigned int)__cvta_generic_to_shared(smem_dst);
  int sz = valid ? 4 : 0;
  asm volatile("cp.async.ca.shared.global [%0], [%1], 4, %2;\n" :: "r"(d), "l"(gsrc), "r"(sz));
}
__device__ __forceinline__ void cp_async16(void* smem_dst, const void* gsrc){
  unsigned int d = (unsigned int)__cvta_generic_to_shared(smem_dst);
  asm volatile("cp.async.cg.shared.global [%0], [%1], 16;\n" :: "r"(d), "l"(gsrc));
}
__device__ __forceinline__ void cp_commit(){ asm volatile("cp.async.commit_group;\n"); }
template<int N> __device__ __forceinline__ void cp_wait(){ asm volatile("cp.async.wait_group %0;\n"::"n"(N)); }

// ---- bf16 pack: lower 16 = bf16(lo_elem), upper 16 = bf16(hi_elem) --------
__device__ __forceinline__ uint32_t packbf(float lo_elem, float hi_elem){
  uint32_t r; asm("cvt.rn.bf16x2.f32 %0, %1, %2;" : "=r"(r) : "f"(hi_elem), "f"(lo_elem)); return r;
}

// ---- warp mma m16n8k16 bf16 ----------------------------------------------
__device__ __forceinline__ void mma_bf16(float& d0,float& d1,float& d2,float& d3,
    uint32_t a0,uint32_t a1,uint32_t a2,uint32_t a3, uint32_t b0,uint32_t b1){
  asm volatile("mma.sync.aligned.m16n8k16.row.col.f32.bf16.bf16.f32 "
    "{%0,%1,%2,%3}, {%4,%5,%6,%7}, {%8,%9}, {%0,%1,%2,%3};"
    : "+f"(d0),"+f"(d1),"+f"(d2),"+f"(d3)
    : "r"(a0),"r"(a1),"r"(a2),"r"(a3),"r"(b0),"r"(b1));
}

// ---------------- head weight transposes (fp32 path) -----------------------
__global__ void wtrans_kernel(const float* __restrict__ dh1, const float* __restrict__ ch1,
                              const float* __restrict__ dh2, const float* __restrict__ dh3){
  int t = blockIdx.y;
  int idx = blockIdx.x*256 + threadIdx.x;
  if (t==0 || t==1){
    const float* src = (t==0)?dh1:ch1;
    float* dst = (t==0)?g_wtd:g_wtc;
    if (idx < 32*288){
      int ic = idx/288; int r = idx - ic*288; int tap = r>>5; int oc = r&31;
      dst[idx] = src[(oc*32+ic)*9+tap];
    }
  } else if (t==2){
    if (idx < 2048) g_wt2[idx] = dh2[(idx&63)*32 + (idx>>6)];
  } else {
    if (idx < 16384) g_wt3[idx] = dh3[(idx&255)*64 + (idx>>8)];
  }
}

// ---------------- GRU weights -> hi/lo bf16 B-fragments --------------------
// zr: nb0-3 = Wz, nb4-7 = Wr | q: nb0-3 = Wq
__global__ void wtrans_frag(const float* __restrict__ Wz, const float* __restrict__ Wr,
                            const float* __restrict__ Wq){
  int idx = blockIdx.x*256 + threadIdx.x;   // 53760 + 26880 = 80640 entries
  if (idx >= 80640) return;
  const float* W; int oc, cc, ver, s, nb, lane;
  uint32_t* dst;
  if (idx < 53760){
    cc = idx/2560; int r = idx%2560;
    ver = r/1280; r %= 1280; s = r/256; r %= 256; nb = r/32; lane = r%32;
    int g = lane>>2;
    W = (nb<4) ? Wz : Wr; oc = (nb&3)*8 + g;
    dst = g_wf + cc*5120 + (((ver*5+s)*8+nb)*32+lane)*2;
  } else {
    int i2 = idx - 53760;
    cc = i2/1280; int r = i2%1280;
    ver = r/640; r %= 640; s = r/128; r %= 128; nb = r/32; lane = r%32;
    int g = lane>>2;
    W = Wq; oc = nb*8 + g;
    dst = g_wf + QOFF + cc*2560 + (((ver*5+s)*4+nb)*32+lane)*2;
  }
  int tt = lane & 3;
  auto wval = [&](int k)->float{
    if (k >= 72) return 0.f;
    int ic = cc*8 + k/9;
    if (ic >= NCT) return 0.f;
    return W[(oc*NCT+ic)*9 + (k%9)];
  };
  int k0 = s*16 + 2*tt;
  float w00 = wval(k0),   w01 = wval(k0+1);
  float w10 = wval(k0+8), w11 = wval(k0+9);
  uint32_t b0, b1;
  if (ver == 0){
    b0 = packbf(w00, w01);
    b1 = packbf(w10, w11);
  } else {
    float h00 = __bfloat162float(__float2bfloat16(w00));
    float h01 = __bfloat162float(__float2bfloat16(w01));
    float h10 = __bfloat162float(__float2bfloat16(w10));
    float h11 = __bfloat162float(__float2bfloat16(w11));
    b0 = packbf(w00-h00, w01-h01);
    b1 = packbf(w10-h10, w11-h11);
  }
  dst[0] = b0; dst[1] = b1;
}

// ============= GRU conv via warp-mma bf16 (hi/lo split) ===================
// MODE 0: fused z+r (N=64): g_z, g_rh
// MODE 1: q        (N=32): h -> out
// CTA 128 thr / 4 warps; tile 32x4 px (warp = tile row), M=128, K=21x80.
template<int MODE>
__global__ void __launch_bounds__(128, (MODE==1)?4:3) uconv(
    const float* __restrict__ in0, const float* __restrict__ depth,
    const float* __restrict__ corr, const float* __restrict__ bias,
    const float* __restrict__ bias2, const float* __restrict__ hidden,
    float* __restrict__ out)
{
  constexpr int NB   = (MODE==1) ? 4 : 8;
  constexpr int SH   = 6;
  constexpr int SW   = 34;
  constexpr int RAWSZ= 8*SH*SW;
  constexpr int WRDS = NB*640;
  constexpr int LOOF = NB*320;

  extern __shared__ __align__(16) unsigned char smx[];
  uint32_t* s_wf = (uint32_t*)smx;
  float*    s_raw= (float*)(smx + 2*WRDS*4);

  const int tid  = threadIdx.x;
  const int wrp  = tid >> 5;
  const int lane = tid & 31;
  const int g    = lane >> 2;
  const int t    = lane & 3;
  const int x0 = blockIdx.x*32, y0 = blockIdx.y*4, b = blockIdx.z;

  const float* i0 = (MODE==1) ? (const float*)g_rh : in0;
  const uint32_t* wsrc = (MODE==0) ? g_wf : (g_wf + QOFF);

  int offA[5][4];
  #pragma unroll
  for (int s=0;s<5;s++){
    #pragma unroll
    for (int j=0;j<4;j++){
      int k = s*16 + 2*t + (j&1) + (j>>1)*8;
      offA[s][j] = (k<72) ? ((k/9)*(SH*SW) + ((k%9)/3)*SW + ((k%9)%3)) : 0;
    }
  }

  auto prefetch = [&](int cc, int buf){
    float* din = s_raw + buf*RAWSZ;
    for (int idx = tid; idx < RAWSZ; idx += 128){
      int icl = idx/(SH*SW);
      int rem = idx - icl*(SH*SW);
      int sy  = rem/SW;
      int sx  = rem - sy*SW;
      int c   = cc*8 + icl;
      int gy  = y0 + sy - 1;
      int gx  = x0 + sx - 1;
      bool ok = (c < NCT) && ((unsigned)gy < IMH) && ((unsigned)gx < IMW);
      int cs  = ok ? c : 0;
      const float* p;
      if (cs < 32)       p = i0    + (size_t)(b*32 + cs)*HWSZ;
      else if (cs == 32) p = depth + (size_t)b*HWSZ;
      else               p = corr  + (size_t)(b*128 + (cs-33))*HWSZ;
      int off = ok ? (gy*IMW + gx) : 0;
      cp_async4(din + idx, p + off, ok);
    }
    const uint4* gsrc = (const uint4*)(wsrc + (size_t)cc*WRDS);
    uint4* dst = (uint4*)(s_wf + buf*WRDS);
    for (int i = tid; i < WRDS/4; i += 128)
      cp_async16(dst + i, gsrc + i);
  };

  float D[2*NB*4];
  #pragma unroll
  for (int i=0;i<2*NB*4;i++) D[i]=0.f;

  prefetch(0, 0); cp_commit();

  for (int cc = 0; cc < NCHUNK; cc++){
    cp_wait<0>();
    __syncthreads();
    if (cc+1 < NCHUNK){ prefetch(cc+1, (cc+1)&1); cp_commit(); }

    const float* raw = s_raw + (cc&1)*RAWSZ + wrp*SW;
    const uint32_t* wf = s_wf + (cc&1)*WRDS;

    #pragma unroll
    for (int s=0;s<5;s++){
      #pragma unroll
      for (int mb=0;mb<2;mb++){
        const float* pA = raw + mb*16 + g;
        const float* pB = pA + 8;
        float vA0 = pA[offA[s][0]], vA1 = pA[offA[s][1]];
        float vB0 = pB[offA[s][0]], vB1 = pB[offA[s][1]];
        uint32_t ah0 = packbf(vA0, vA1);
        uint32_t ah1 = packbf(vB0, vB1);
        float hA0 = __uint_as_float(ah0<<16), hA1 = __uint_as_float(ah0 & 0xffff0000u);
        float hB0 = __uint_as_float(ah1<<16), hB1 = __uint_as_float(ah1 & 0xffff0000u);
        uint32_t al0 = packbf(vA0-hA0, vA1-hA1);
        uint32_t al1 = packbf(vB0-hB0, vB1-hB1);
        uint32_t ah2=0, ah3=0, al2=0, al3=0;
        if (s < 4){
          float wA0 = pA[offA[s][2]], wA1 = pA[offA[s][3]];
          float wB0 = pB[offA[s][2]], wB1 = pB[offA[s][3]];
          ah2 = packbf(wA0, wA1);
          ah3 = packbf(wB0, wB1);
          float qA0 = __uint_as_float(ah2<<16), qA1 = __uint_as_float(ah2 & 0xffff0000u);
          float qB0 = __uint_as_float(ah3<<16), qB1 = __uint_as_float(ah3 & 0xffff0000u);
          al2 = packbf(wA0-qA0, wA1-qA1);
          al3 = packbf(wB0-qB0, wB1-qB1);
        }
        #pragma unroll
        for (int nb=0;nb<NB;nb++){
          uint2 bh = *(const uint2*)(wf + (s*NB+nb)*64 + lane*2);
          uint2 bl = *(const uint2*)(wf + LOOF + (s*NB+nb)*64 + lane*2);
          float* dd = &D[(mb*NB+nb)*4];
          mma_bf16(dd[0],dd[1],dd[2],dd[3], ah0,ah1,ah2,ah3, bh.x,bh.y);
          mma_bf16(dd[0],dd[1],dd[2],dd[3], ah0,ah1,ah2,ah3, bl.x,bl.y);
          mma_bf16(dd[0],dd[1],dd[2],dd[3], al0,al1,al2,al3, bh.x,bh.y);
        }
      }
    }
  }

  // epilogue. D frag: d0:(g,2t) d1:(g,2t+1) d2:(g+8,2t) d3:(g+8,2t+1)
  const int y = y0 + wrp;
  if (MODE==0){
    #pragma unroll
    for (int mb=0;mb<2;mb++){
      int xA = x0 + mb*16 + g;
      #pragma unroll
      for (int nb=0;nb<8;nb++){
        float* dd = &D[(mb*8+nb)*4];
        int oc0 = (nb&3)*8 + 2*t;
        float b0v = (nb<4) ? __ldg(bias+oc0)   : __ldg(bias2+oc0);
        float b1v = (nb<4) ? __ldg(bias+oc0+1) : __ldg(bias2+oc0+1);
        int gi0 = ((b*32+oc0)*IMH + y)*IMW + xA;
        int gi1 = gi0 + HWSZ;
        if (nb<4){
          g_z[gi0]   = sigmoidf_(dd[0] + b0v);
          g_z[gi1]   = sigmoidf_(dd[1] + b1v);
          g_z[gi0+8] = sigmoidf_(dd[2] + b0v);
          g_z[gi1+8] = sigmoidf_(dd[3] + b1v);
        } else {
          g_rh[gi0]   = sigmoidf_(dd[0] + b0v) * __ldg(hidden+gi0);
          g_rh[gi1]   = sigmoidf_(dd[1] + b1v) * __ldg(hidden+gi1);
          g_rh[gi0+8] = sigmoidf_(dd[2] + b0v) * __ldg(hidden+gi0+8);
          g_rh[gi1+8] = sigmoidf_(dd[3] + b1v) * __ldg(hidden+gi1+8);
        }
      }
    }
  } else {
    #pragma unroll
    for (int mb=0;mb<2;mb++){
      int xA = x0 + mb*16 + g;
      #pragma unroll
      for (int nb=0;nb<4;nb++){
        float* dd = &D[(mb*4+nb)*4];
        int oc0 = nb*8 + 2*t;
        float b0v = __ldg(bias+oc0), b1v = __ldg(bias+oc0+1);
        int gi0 = ((b*32+oc0)*IMH + y)*IMW + xA;
        int gi1 = gi0 + HWSZ;
        #pragma unroll
        for (int e=0;e<4;e++){
          int gi = (e&1) ? gi1 : gi0;
          gi += (e>>1)*8;
          float v = dd[e] + ((e&1)?b1v:b0v);
          float q  = tanhf(v);
          float z  = g_z[gi];
          float h0 = __ldg(hidden+gi);
          out[gi] = h0 + z*(q - h0);
        }
      }
    }
  }
}

// ============= head convs (Cin=32, dil=2) — fp32 f32x2 pipelined ==========
// MODE 3: c1=relu(conv(h,ch1,dil2)); c0=ch2.c1+cb2   -> out(c0), out2(conf)
// MODE 4: d1=relu(conv(h,dh1,dil2))                  -> g_d1
template<int MODE>
__global__ void __launch_bounds__(256,2) conv_pipe(
    const float* __restrict__ in_h,
    const float* __restrict__ aux, const float* __restrict__ aux2,
    float* __restrict__ out, float* __restrict__ out2)
{
  constexpr int DIL = 2;
  constexpr int SH  = 20;
  constexpr int SW  = 36;
  constexpr int CH  = 8;
  constexpr int TILE = CH*SH*SW;
  constexpr int WCH  = CH*288;
  constexpr int NC   = 4;

  extern __shared__ float sm[];
  float* s_in  = sm;
  float* s_w   = sm + 2*TILE;
  float* s_red = s_w + 2*WCH;

  const int tid = threadIdx.x;
  const int x   = tid & 31;
  const int ty  = (tid >> 5) & 3;
  const int oh  = tid >> 7;
  const int ty4 = ty*4;
  const int x0  = blockIdx.x*32;
  const int y0  = blockIdx.y*16;
  const int b   = blockIdx.z;

  const float* WtT = (MODE==3) ? g_wtc : g_wtd;

  auto prefetch = [&](int cc, int buf){
    int c0 = cc*CH;
    float* din = s_in + buf*TILE;
    float* dw  = s_w  + buf*WCH;
    for (int idx = tid; idx < TILE; idx += 256){
      int icl = idx/(SH*SW);
      int rem = idx - icl*(SH*SW);
      int sy  = rem/SW;
      int sx  = rem - sy*SW;
      int c   = c0+icl;
      int gy  = y0 + sy - DIL;
      int gx  = x0 + sx - DIL;
      bool ok = ((unsigned)gy < IMH) && ((unsigned)gx < IMW);
      const float* p = in_h + (size_t)(b*32 + c)*HWSZ;
      int off = ok ? (gy*IMW + gx) : 0;
      cp_async4(din + idx, p + off, ok);
    }
    int wbase = c0*288;
    for (int idx = tid; idx < WCH; idx += 256)
      cp_async4(dw + idx, WtT + wbase + idx, true);
  };

  unsigned long long acc[4][8];
  #pragma unroll
  for (int j=0;j<4;j++)
    #pragma unroll
    for (int o=0;o<8;o++) acc[j][o] = 0ull;

  prefetch(0, 0); cp_commit();

  for (int cc=0; cc<NC; cc++){
    if (cc+1 < NC){ prefetch(cc+1, (cc+1)&1); cp_commit(); cp_wait<1>(); }
    else          { cp_wait<0>(); }
    __syncthreads();

    const float* sin = s_in + (cc&1)*TILE;
    const float* sw  = s_w  + (cc&1)*WCH;

    for (int dy=0; dy<3; dy++){
      #pragma unroll
      for (int dx=0; dx<3; dx++){
        #pragma unroll 2
        for (int icl=0; icl<CH; icl++){
          int ibase = icl*(SH*SW) + (dy*DIL)*SW + x + dx*DIL;
          float v0 = sin[ibase + (ty4+0)*SW];
          float v1 = sin[ibase + (ty4+1)*SW];
          float v2 = sin[ibase + (ty4+2)*SW];
          float v3 = sin[ibase + (ty4+3)*SW];
          unsigned long long vv0 = pack2(v0,v0);
          unsigned long long vv1 = pack2(v1,v1);
          unsigned long long vv2 = pack2(v2,v2);
          unsigned long long vv3 = pack2(v3,v3);
          const float* wrow = &sw[(icl*9 + dy*3 + dx)*32 + oh*16];
          #pragma unroll
          for (int op=0; op<8; op++){
            unsigned long long wp = *(const unsigned long long*)(wrow + 2*op);
            ffma2(acc[0][op], vv0, wp);
            ffma2(acc[1][op], vv1, wp);
            ffma2(acc[2][op], vv2, wp);
            ffma2(acc[3][op], vv3, wp);
          }
        }
      }
    }
    __syncthreads();
  }

  const int xg = x0 + x;
  if (MODE==3){
    float part[4];
    #pragma unroll
    for (int j=0;j<4;j++){
      float cv = 0.f;
      #pragma unroll
      for (int op=0; op<8; op++){
        int oc = oh*16 + 2*op;
        float2 a = unpack2(acc[j][op]);
        cv = fmaf(__ldg(aux+oc),   fmaxf(a.x,0.f), cv);
        cv = fmaf(__ldg(aux+oc+1), fmaxf(a.y,0.f), cv);
      }
      part[j] = cv;
    }
    if (oh==0){
      #pragma unroll
      for (int j=0;j<4;j++) s_red[(ty4+j)*32 + x] = part[j];
    }
    __syncthreads();
    if (oh==1){
      float cb = __ldg(aux2);
      #pragma unroll
      for (int j=0;j<4;j++){
        int y = y0+ty4+j;
        float cv = part[j] + s_red[(ty4+j)*32 + x] + cb;
        int pidx = (b*IMH + y)*IMW + xg;
        out [pidx] = cv;
        out2[pidx] = sigmoidf_(cv);
      }
    }
  } else {
    #pragma unroll
    for (int j=0;j<4;j++){
      int y = y0+ty4+j;
      #pragma unroll
      for (int op=0; op<8; op++){
        int oc = oh*16 + 2*op;
        float2 a = unpack2(acc[j][op]);
        int g0 = ((b*32+oc)*IMH + y)*IMW + xg;
        g_d1[g0]      = fmaxf(a.x, 0.f);
        g_d1[g0+HWSZ] = fmaxf(a.y, 0.f);
      }
    }
  }
}

// ---------------- dh2 + dh3 GEMM + softmax + argmax regression ------------
__global__ void __launch_bounds__(256) head_kernel(
    const float* __restrict__ db3,
    float* __restrict__ prob, float* __restrict__ nd)
{
  extern __shared__ float sm[];
  float* s_w3t = sm;             // 16384
  float* s_w2t = sm + 16384;     // 2048
  float* s_db3 = sm + 18432;     // 256
  float* s_d1  = sm + 18688;     // 2048
  float* s_d2  = sm + 20736;     // 4096
  float* s_l   = sm + 24832;     // 16640
  float* s_inv = sm + 41472;     // 64

  const int tid  = threadIdx.x;
  const int lane = tid & 31;
  const int g    = tid >> 5;
  const int y    = blockIdx.x;
  const int b    = blockIdx.y;

  for (int i = tid; i < 16384; i += 256) s_w3t[i] = g_wt3[i];
  for (int i = tid; i < 2048;  i += 256) s_w2t[i] = g_wt2[i];
  if (tid < 256) s_db3[tid] = db3[tid];
  __syncthreads();

  for (int xt = 0; xt < 5; xt++){
    int x0 = xt*64;
    for (int i = tid; i < 2048; i += 256){
      int ch = i >> 6, xp = i & 63;
      s_d1[i] = g_d1[((b*32+ch)*IMH + y)*IMW + x0 + xp];
    }
    __syncthreads();

    {
      int px  = tid & 63;
      int grp = tid >> 6;
      unsigned long long a2[8];
      #pragma unroll
      for (int k=0;k<8;k++) a2[k]=0ull;
      #pragma unroll 4
      for (int ic=0; ic<32; ic++){
        float v = s_d1[ic*64 + px];
        unsigned long long vv = pack2(v,v);
        const float* wr = &s_w2t[ic*64 + grp*16];
        #pragma unroll
        for (int k=0;k<8;k++){
          unsigned long long wp = *(const unsigned long long*)(wr + 2*k);
          ffma2(a2[k], vv, wp);
        }
      }
      #pragma unroll
      for (int k=0;k<8;k++){
        float2 a = unpack2(a2[k]);
        int oc2 = grp*16 + 2*k;
        s_d2[oc2*64 + px]     = fmaxf(a.x, 0.f);
        s_d2[(oc2+1)*64 + px] = fmaxf(a.y, 0.f);
      }
    }
    __syncthreads();

    {
      unsigned long long a0[16], a1[16];
      #pragma unroll
      for (int k=0;k<16;k++){ a0[k]=0ull; a1[k]=0ull; }
      int x1 = lane, x2 = lane+32;
      #pragma unroll 4
      for (int ic=0; ic<64; ic++){
        float v0 = s_d2[ic*64 + x1];
        float v1 = s_d2[ic*64 + x2];
        unsigned long long vv0 = pack2(v0,v0);
        unsigned long long vv1 = pack2(v1,v1);
        const float* wr = &s_w3t[ic*256 + g*32];
        #pragma unroll
        for (int k=0;k<16;k++){
          unsigned long long wp = *(const unsigned long long*)(wr + 2*k);
          ffma2(a0[k], vv0, wp);
          ffma2(a1[k], vv1, wp);
        }
      }
      #pragma unroll
      for (int k=0;k<16;k++){
        int oc = g*32 + 2*k;
        float2 p0 = unpack2(a0[k]);
        float2 p1 = unpack2(a1[k]);
        float ba = s_db3[oc], bb = s_db3[oc+1];
        s_l[oc*65 + x1]     = p0.x + ba;
        s_l[(oc+1)*65 + x1] = p0.y + bb;
        s_l[oc*65 + x2]     = p1.x + ba;
        s_l[(oc+1)*65 + x2] = p1.y + bb;
      }
    }
    __syncthreads();

    for (int p8 = 0; p8 < 8; p8++){
      int px = g*8 + p8;
      float lv[8];
      float m = -INFINITY; int mi = 0;
      #pragma unroll
      for (int k=0;k<8;k++){
        int oc = lane + k*32;
        lv[k] = s_l[oc*65 + px];
        if (lv[k] > m){ m = lv[k]; mi = oc; }
      }
      #pragma unroll
      for (int off=16; off; off>>=1){
        float om = __shfl_xor_sync(0xffffffffu, m,  off);
        int   oi = __shfl_xor_sync(0xffffffffu, mi, off);
        if (om > m || (om == m && oi < mi)){ m = om; mi = oi; }
      }
      float ssum = 0.f;
      #pragma unroll
      for (int k=0;k<8;k++){
        float e = __expf(lv[k] - m);
        s_l[(lane + k*32)*65 + px] = e;
        ssum += e;
      }
      #pragma unroll
      for (int off=16; off; off>>=1) ssum += __shfl_xor_sync(0xffffffffu, ssum, off);
      float inv = 1.f/ssum;
      __syncwarp();
      float aa = 0.f, bb = 0.f;
      if (lane < 9){
        int ocw = mi - 4 + lane;
        ocw = max(0, min(255, ocw));
        float pw = s_l[ocw*65 + px] * inv;
        aa = (float)ocw * pw;
        bb = pw;
      }
      #pragma unroll
      for (int off=16; off; off>>=1){
        aa += __shfl_xor_sync(0xffffffffu, aa, off);
        bb += __shfl_xor_sync(0xffffffffu, bb, off);
      }
      if (lane == 0){
        s_inv[px] = inv;
        nd[(b*IMH + y)*IMW + x0 + px] = (aa/(1e-6f + bb)) * (1.f/255.f);
      }
    }
    __syncthreads();

    for (int i = tid; i < 16384; i += 256){
      int oc = i >> 6, xp = i & 63;
      prob[((b*256+oc)*IMH + y)*IMW + x0 + xp] = s_l[oc*65 + xp] * s_inv[xp];
    }
    __syncthreads();
  }
}

// ---------------- launch ---------------------------------------------------
extern "C" void kernel_launch(void* const* d_in, const int* in_sizes, int n_in,
                              void* d_out, int out_size)
{
  const float* hidden = (const float*)d_in[0];
  const float* depth  = (const float*)d_in[1];
  const float* corr   = (const float*)d_in[2];
  const float* Wz  = (const float*)d_in[3];
  const float* bz  = (const float*)d_in[4];
  const float* Wr  = (const float*)d_in[5];
  const float* br  = (const float*)d_in[6];
  const float* Wq  = (const float*)d_in[7];
  const float* bq  = (const float*)d_in[8];
  const float* dh1 = (const float*)d_in[9];
  const float* dh2 = (const float*)d_in[10];
  const float* dh3 = (const float*)d_in[11];
  const float* db3 = (const float*)d_in[12];
  const float* ch1 = (const float*)d_in[13];
  const float* ch2 = (const float*)d_in[14];
  const float* cb2 = (const float*)d_in[15];

  float* out      = (float*)d_out;
  float* h_out    = out;
  float* nd_out   = h_out   + (size_t)BB*32*HWSZ;
  float* prob_out = nd_out  + (size_t)BB*HWSZ;
  float* conf_out = prob_out+ (size_t)BB*256*HWSZ;
  float* c0_out   = conf_out+ (size_t)BB*HWSZ;

  const int SM0 = 2*5120*4 + 2*(8*6*34)*4;   // 40960 + 13056 = 54016
  const int SM1 = 2*2560*4 + 2*(8*6*34)*4;   // 20480 + 13056 = 33536
  const int SM_HEADC = (2*(8*20*36) + 2*(8*288) + 512) * 4;   // 66560
  cudaFuncSetAttribute(uconv<0>, cudaFuncAttributeMaxDynamicSharedMemorySize, SM0);
  cudaFuncSetAttribute(uconv<1>, cudaFuncAttributeMaxDynamicSharedMemorySize, SM1);
  cudaFuncSetAttribute(conv_pipe<3>, cudaFuncAttributeMaxDynamicSharedMemorySize, SM_HEADC);
  cudaFuncSetAttribute(conv_pipe<4>, cudaFuncAttributeMaxDynamicSharedMemorySize, SM_HEADC);
  cudaFuncSetAttribute(head_kernel, cudaFuncAttributeMaxDynamicSharedMemorySize, 41536*4);

  wtrans_kernel<<<dim3(64,4), 256>>>(dh1, ch1, dh2, dh3);
  wtrans_frag<<<(80640 + 255)/256, 256>>>(Wz, Wr, Wq);

  dim3 gg(IMW/32, IMH/4, BB);
  uconv<0><<<gg,128,SM0>>>(hidden, depth, corr, bz, br, hidden, nullptr);
  uconv<1><<<gg,128,SM1>>>(nullptr, depth, corr, bq, nullptr, hidden, h_out);

  dim3 cg(IMW/32, IMH/16, BB);
  conv_pipe<3><<<cg,256,SM_HEADC>>>(h_out, ch2, cb2, c0_out, conf_out);
  conv_pipe<4><<<cg,256,SM_HEADC>>>(h_out, nullptr, nullptr, nullptr, nullptr);

  head_kernel<<<dim3(IMH, BB), 256, 41536*4>>>(db3, prob_out, nd_out);
}

// round 15
// speedup vs baseline: 1.7452x; 1.0547x over previous
#include <cuda_runtime.h>
#include <cuda_bf16.h>
#include <math.h>
#include <stdint.h>

#define IMH 256
#define IMW 320
#define HWSZ (IMH*IMW)
#define BB 4
#define NCT 161
#define NCHUNK 21

// frag table offsets (32-bit words)
#define QOFF   107520        // 21*5120
#define CH1OFF 161280        // QOFF + 21*2560

// ---------------- scratch (device globals; no allocation allowed) ----------
__device__ float g_z [BB*32*HWSZ];
__device__ float g_rh[BB*32*HWSZ];
__device__ float g_d1[BB*32*HWSZ];
__device__ float g_wtd[32*9*32];
__device__ float g_wt2[32*64];    // dh2^T  [ic][oc2]
__device__ float g_wt3[64*256];   // dh3^T  [ic][oc]
// B fragments: zr [21][2][5][8][32][2] | q [21][2][5][4][32][2] | ch1 [4][2][5][4][32][2]
__device__ uint32_t g_wf[171520];

__device__ __forceinline__ float sigmoidf_(float v){ return 1.f/(1.f+__expf(-v)); }

// ---- packed fp32x2 helpers ------------------------------------------------
__device__ __forceinline__ unsigned long long pack2(float a, float b){
  unsigned long long r; asm("mov.b64 %0,{%1,%2};":"=l"(r):"f"(a),"f"(b)); return r;
}
__device__ __forceinline__ void ffma2(unsigned long long& d, unsigned long long a, unsigned long long b){
  asm("fma.rn.f32x2 %0, %1, %2, %0;":"+l"(d):"l"(a),"l"(b));
}
__device__ __forceinline__ float2 unpack2(unsigned long long v){
  float2 r; asm("mov.b64 {%0,%1}, %2;":"=f"(r.x),"=f"(r.y):"l"(v)); return r;
}

// ---- cp.async helpers -----------------------------------------------------
__device__ __forceinline__ void cp_async4(float* smem_dst, const float* gsrc, bool valid){
  unsigned int d = (unsigned int)__cvta_generic_to_shared(smem_dst);
  int sz = valid ? 4 : 0;
  asm volatile("cp.async.ca.shared.global [%0], [%1], 4, %2;\n" :: "r"(d), "l"(gsrc), "r"(sz));
}
__device__ __forceinline__ void cp_async16(void* smem_dst, const void* gsrc){
  unsigned int d = (unsigned int)__cvta_generic_to_shared(smem_dst);
  asm volatile("cp.async.cg.shared.global [%0], [%1], 16;\n" :: "r"(d), "l"(gsrc));
}
__device__ __forceinline__ void cp_commit(){ asm volatile("cp.async.commit_group;\n"); }
template<int N> __device__ __forceinline__ void cp_wait(){ asm volatile("cp.async.wait_group %0;\n"::"n"(N)); }

// ---- bf16 pack: lower 16 = bf16(lo_elem), upper 16 = bf16(hi_elem) --------
__device__ __forceinline__ uint32_t packbf(float lo_elem, float hi_elem){
  uint32_t r; asm("cvt.rn.bf16x2.f32 %0, %1, %2;" : "=r"(r) : "f"(hi_elem), "f"(lo_elem)); return r;
}

// ---- warp mma m16n8k16 bf16 ----------------------------------------------
__device__ __forceinline__ void mma_bf16(float& d0,float& d1,float& d2,float& d3,
    uint32_t a0,uint32_t a1,uint32_t a2,uint32_t a3, uint32_t b0,uint32_t b1){
  asm volatile("mma.sync.aligned.m16n8k16.row.col.f32.bf16.bf16.f32 "
    "{%0,%1,%2,%3}, {%4,%5,%6,%7}, {%8,%9}, {%0,%1,%2,%3};"
    : "+f"(d0),"+f"(d1),"+f"(d2),"+f"(d3)
    : "r"(a0),"r"(a1),"r"(a2),"r"(a3),"r"(b0),"r"(b1));
}

// ---------------- head weight transposes (fp32 path) -----------------------
__global__ void wtrans_kernel(const float* __restrict__ dh1,
                              const float* __restrict__ dh2, const float* __restrict__ dh3){
  int t = blockIdx.y;
  int idx = blockIdx.x*256 + threadIdx.x;
  if (t==0){
    if (idx < 32*288){
      int ic = idx/288; int r = idx - ic*288; int tap = r>>5; int oc = r&31;
      g_wtd[idx] = dh1[(oc*32+ic)*9+tap];
    }
  } else if (t==1){
    if (idx < 2048) g_wt2[idx] = dh2[(idx&63)*32 + (idx>>6)];
  } else {
    if (idx < 16384) g_wt3[idx] = dh3[(idx&255)*64 + (idx>>8)];
  }
}

// ---------------- conv weights -> hi/lo bf16 B-fragments -------------------
// zr: nb0-3 = Wz, nb4-7 = Wr | q: nb0-3 = Wq | ch1: nb0-3 = ch1
__global__ void wtrans_frag(const float* __restrict__ Wz, const float* __restrict__ Wr,
                            const float* __restrict__ Wq, const float* __restrict__ ch1){
  int idx = blockIdx.x*256 + threadIdx.x;   // 53760 + 26880 + 5120 = 85760 entries
  if (idx >= 85760) return;
  const float* W; int cin, oc, cc, ver, s, nb, lane;
  uint32_t* dst;
  if (idx < 53760){
    cc = idx/2560; int r = idx%2560;
    ver = r/1280; r %= 1280; s = r/256; r %= 256; nb = r/32; lane = r%32;
    int g = lane>>2;
    W = (nb<4) ? Wz : Wr; cin = NCT; oc = (nb&3)*8 + g;
    dst = g_wf + cc*5120 + (((ver*5+s)*8+nb)*32+lane)*2;
  } else if (idx < 80640){
    int i2 = idx - 53760;
    cc = i2/1280; int r = i2%1280;
    ver = r/640; r %= 640; s = r/128; r %= 128; nb = r/32; lane = r%32;
    int g = lane>>2;
    W = Wq; cin = NCT; oc = nb*8 + g;
    dst = g_wf + QOFF + cc*2560 + (((ver*5+s)*4+nb)*32+lane)*2;
  } else {
    int i2 = idx - 80640;
    cc = i2/1280; int r = i2%1280;
    ver = r/640; r %= 640; s = r/128; r %= 128; nb = r/32; lane = r%32;
    int g = lane>>2;
    W = ch1; cin = 32; oc = nb*8 + g;
    dst = g_wf + CH1OFF + cc*2560 + (((ver*5+s)*4+nb)*32+lane)*2;
  }
  int tt = lane & 3;
  auto wval = [&](int k)->float{
    if (k >= 72) return 0.f;
    int ic = cc*8 + k/9;
    if (ic >= cin) return 0.f;
    return W[(oc*cin+ic)*9 + (k%9)];
  };
  int k0 = s*16 + 2*tt;
  float w00 = wval(k0),   w01 = wval(k0+1);
  float w10 = wval(k0+8), w11 = wval(k0+9);
  uint32_t b0, b1;
  if (ver == 0){
    b0 = packbf(w00, w01);
    b1 = packbf(w10, w11);
  } else {
    float h00 = __bfloat162float(__float2bfloat16(w00));
    float h01 = __bfloat162float(__float2bfloat16(w01));
    float h10 = __bfloat162float(__float2bfloat16(w10));
    float h11 = __bfloat162float(__float2bfloat16(w11));
    b0 = packbf(w00-h00, w01-h01);
    b1 = packbf(w10-h10, w11-h11);
  }
  dst[0] = b0; dst[1] = b1;
}

// ============= convs via warp-mma bf16 (hi/lo split) ======================
// MODE 0: fused z+r (N=64, DIL=1, CIN=161): g_z, g_rh
// MODE 1: q        (N=32, DIL=1, CIN=161): h -> out
// MODE 2: conf head (N=32, DIL=2, CIN=32): c0 -> out, conf -> out2
// CTA 128 thr / 4 warps; tile 32x4 px (warp = tile row), M=128.
template<int MODE>
__global__ void __launch_bounds__(128, (MODE==0)?3:4) uconv(
    const float* __restrict__ in0, const float* __restrict__ depth,
    const float* __restrict__ corr, const float* __restrict__ bias,
    const float* __restrict__ bias2, const float* __restrict__ hidden,
    const float* __restrict__ aux, const float* __restrict__ aux2,
    float* __restrict__ out, float* __restrict__ out2)
{
  constexpr int DIL  = (MODE==2) ? 2 : 1;
  constexpr int CIN  = (MODE==2) ? 32 : NCT;
  constexpr int NCH  = (MODE==2) ? 4 : NCHUNK;
  constexpr int NB   = (MODE==0) ? 8 : 4;
  constexpr int SH   = 4 + 2*DIL;
  constexpr int SW   = 32 + 2*DIL;
  constexpr int RAWSZ= 8*SH*SW;
  constexpr int WRDS = NB*640;
  constexpr int LOOF = NB*320;

  extern __shared__ __align__(16) unsigned char smx[];
  uint32_t* s_wf = (uint32_t*)smx;
  float*    s_raw= (float*)(smx + 2*WRDS*4);

  const int tid  = threadIdx.x;
  const int wrp  = tid >> 5;
  const int lane = tid & 31;
  const int g    = lane >> 2;
  const int t    = lane & 3;
  const int x0 = blockIdx.x*32, y0 = blockIdx.y*4, b = blockIdx.z;

  const float* i0 = (MODE==1) ? (const float*)g_rh : in0;
  const uint32_t* wsrc = (MODE==0) ? g_wf : ((MODE==1) ? (g_wf + QOFF) : (g_wf + CH1OFF));

  int offA[5][4];
  #pragma unroll
  for (int s=0;s<5;s++){
    #pragma unroll
    for (int j=0;j<4;j++){
      int k = s*16 + 2*t + (j&1) + (j>>1)*8;
      offA[s][j] = (k<72) ? ((k/9)*(SH*SW) + ((k%9)/3)*DIL*SW + ((k%9)%3)*DIL) : 0;
    }
  }

  auto prefetch = [&](int cc, int buf){
    float* din = s_raw + buf*RAWSZ;
    for (int idx = tid; idx < RAWSZ; idx += 128){
      int icl = idx/(SH*SW);
      int rem = idx - icl*(SH*SW);
      int sy  = rem/SW;
      int sx  = rem - sy*SW;
      int c   = cc*8 + icl;
      int gy  = y0 + sy - DIL;
      int gx  = x0 + sx - DIL;
      bool ok = (c < CIN) && ((unsigned)gy < IMH) && ((unsigned)gx < IMW);
      int cs  = ok ? c : 0;
      const float* p;
      if (MODE==2)       p = in0  + (size_t)(b*32 + cs)*HWSZ;
      else if (cs < 32)  p = i0   + (size_t)(b*32 + cs)*HWSZ;
      else if (cs == 32) p = depth+ (size_t)b*HWSZ;
      else               p = corr + (size_t)(b*128 + (cs-33))*HWSZ;
      int off = ok ? (gy*IMW + gx) : 0;
      cp_async4(din + idx, p + off, ok);
    }
    const uint4* gsrc = (const uint4*)(wsrc + (size_t)cc*WRDS);
    uint4* dst = (uint4*)(s_wf + buf*WRDS);
    for (int i = tid; i < WRDS/4; i += 128)
      cp_async16(dst + i, gsrc + i);
  };

  float D[2*NB*4];
  #pragma unroll
  for (int i=0;i<2*NB*4;i++) D[i]=0.f;

  prefetch(0, 0); cp_commit();

  for (int cc = 0; cc < NCH; cc++){
    cp_wait<0>();
    __syncthreads();
    if (cc+1 < NCH){ prefetch(cc+1, (cc+1)&1); cp_commit(); }

    const float* raw = s_raw + (cc&1)*RAWSZ + wrp*SW;
    const uint32_t* wf = s_wf + (cc&1)*WRDS;

    #pragma unroll
    for (int s=0;s<5;s++){
      #pragma unroll
      for (int mb=0;mb<2;mb++){
        const float* pA = raw + mb*16 + g;
        const float* pB = pA + 8;
        float vA0 = pA[offA[s][0]], vA1 = pA[offA[s][1]];
        float vB0 = pB[offA[s][0]], vB1 = pB[offA[s][1]];
        uint32_t ah0 = packbf(vA0, vA1);
        uint32_t ah1 = packbf(vB0, vB1);
        float hA0 = __uint_as_float(ah0<<16), hA1 = __uint_as_float(ah0 & 0xffff0000u);
        float hB0 = __uint_as_float(ah1<<16), hB1 = __uint_as_float(ah1 & 0xffff0000u);
        uint32_t al0 = packbf(vA0-hA0, vA1-hA1);
        uint32_t al1 = packbf(vB0-hB0, vB1-hB1);
        uint32_t ah2=0, ah3=0, al2=0, al3=0;
        if (s < 4){
          float wA0 = pA[offA[s][2]], wA1 = pA[offA[s][3]];
          float wB0 = pB[offA[s][2]], wB1 = pB[offA[s][3]];
          ah2 = packbf(wA0, wA1);
          ah3 = packbf(wB0, wB1);
          float qA0 = __uint_as_float(ah2<<16), qA1 = __uint_as_float(ah2 & 0xffff0000u);
          float qB0 = __uint_as_float(ah3<<16), qB1 = __uint_as_float(ah3 & 0xffff0000u);
          al2 = packbf(wA0-qA0, wA1-qA1);
          al3 = packbf(wB0-qB0, wB1-qB1);
        }
        #pragma unroll
        for (int nb=0;nb<NB;nb++){
          uint2 bh = *(const uint2*)(wf + (s*NB+nb)*64 + lane*2);
          uint2 bl = *(const uint2*)(wf + LOOF + (s*NB+nb)*64 + lane*2);
          float* dd = &D[(mb*NB+nb)*4];
          mma_bf16(dd[0],dd[1],dd[2],dd[3], ah0,ah1,ah2,ah3, bh.x,bh.y);
          mma_bf16(dd[0],dd[1],dd[2],dd[3], ah0,ah1,ah2,ah3, bl.x,bl.y);
          mma_bf16(dd[0],dd[1],dd[2],dd[3], al0,al1,al2,al3, bh.x,bh.y);
        }
      }
    }
  }

  // epilogue. D frag: d0:(g,2t) d1:(g,2t+1) d2:(g+8,2t) d3:(g+8,2t+1)
  const int y = y0 + wrp;
  if (MODE==0){
    #pragma unroll
    for (int mb=0;mb<2;mb++){
      int xA = x0 + mb*16 + g;
      #pragma unroll
      for (int nb=0;nb<8;nb++){
        float* dd = &D[(mb*8+nb)*4];
        int oc0 = (nb&3)*8 + 2*t;
        float b0v = (nb<4) ? __ldg(bias+oc0)   : __ldg(bias2+oc0);
        float b1v = (nb<4) ? __ldg(bias+oc0+1) : __ldg(bias2+oc0+1);
        int gi0 = ((b*32+oc0)*IMH + y)*IMW + xA;
        int gi1 = gi0 + HWSZ;
        if (nb<4){
          g_z[gi0]   = sigmoidf_(dd[0] + b0v);
          g_z[gi1]   = sigmoidf_(dd[1] + b1v);
          g_z[gi0+8] = sigmoidf_(dd[2] + b0v);
          g_z[gi1+8] = sigmoidf_(dd[3] + b1v);
        } else {
          g_rh[gi0]   = sigmoidf_(dd[0] + b0v) * __ldg(hidden+gi0);
          g_rh[gi1]   = sigmoidf_(dd[1] + b1v) * __ldg(hidden+gi1);
          g_rh[gi0+8] = sigmoidf_(dd[2] + b0v) * __ldg(hidden+gi0+8);
          g_rh[gi1+8] = sigmoidf_(dd[3] + b1v) * __ldg(hidden+gi1+8);
        }
      }
    }
  } else if (MODE==1){
    #pragma unroll
    for (int mb=0;mb<2;mb++){
      int xA = x0 + mb*16 + g;
      #pragma unroll
      for (int nb=0;nb<4;nb++){
        float* dd = &D[(mb*4+nb)*4];
        int oc0 = nb*8 + 2*t;
        float b0v = __ldg(bias+oc0), b1v = __ldg(bias+oc0+1);
        int gi0 = ((b*32+oc0)*IMH + y)*IMW + xA;
        int gi1 = gi0 + HWSZ;
        #pragma unroll
        for (int e=0;e<4;e++){
          int gi = (e&1) ? gi1 : gi0;
          gi += (e>>1)*8;
          float v = dd[e] + ((e&1)?b1v:b0v);
          float q  = tanhf(v);
          float z  = g_z[gi];
          float h0 = __ldg(hidden+gi);
          out[gi] = h0 + z*(q - h0);
        }
      }
    }
  } else {
    float cb = __ldg(aux2);
    #pragma unroll
    for (int mb=0;mb<2;mb++){
      int xA = x0 + mb*16 + g;
      float cr0 = 0.f, cr1 = 0.f;
      #pragma unroll
      for (int nb=0;nb<4;nb++){
        float* dd = &D[(mb*4+nb)*4];
        int oc0 = nb*8 + 2*t;
        float c0w = __ldg(aux+oc0), c1w = __ldg(aux+oc0+1);
        cr0 = fmaf(c0w, fmaxf(dd[0],0.f), fmaf(c1w, fmaxf(dd[1],0.f), cr0));
        cr1 = fmaf(c0w, fmaxf(dd[2],0.f), fmaf(c1w, fmaxf(dd[3],0.f), cr1));
      }
      cr0 += __shfl_xor_sync(0xffffffffu, cr0, 1);
      cr0 += __shfl_xor_sync(0xffffffffu, cr0, 2);
      cr1 += __shfl_xor_sync(0xffffffffu, cr1, 1);
      cr1 += __shfl_xor_sync(0xffffffffu, cr1, 2);
      if (t == 0){
        int p0 = (b*IMH + y)*IMW + xA;
        float v0 = cr0 + cb, v1 = cr1 + cb;
        out [p0]   = v0;  out2[p0]   = sigmoidf_(v0);
        out [p0+8] = v1;  out2[p0+8] = sigmoidf_(v1);
      }
    }
  }
}

// ============= d1 conv (Cin=32, dil=2) — fp32 f32x2 (argmax-critical) =====
__global__ void __launch_bounds__(256,2) conv_d1(const float* __restrict__ in_h)
{
  constexpr int DIL = 2;
  constexpr int SH  = 20;
  constexpr int SW  = 36;
  constexpr int CH  = 8;
  constexpr int TILE = CH*SH*SW;
  constexpr int WCH  = CH*288;
  constexpr int NC   = 4;

  extern __shared__ float sm[];
  float* s_in  = sm;
  float* s_w   = sm + 2*TILE;

  const int tid = threadIdx.x;
  const int x   = tid & 31;
  const int ty  = (tid >> 5) & 3;
  const int oh  = tid >> 7;
  const int ty4 = ty*4;
  const int x0  = blockIdx.x*32;
  const int y0  = blockIdx.y*16;
  const int b   = blockIdx.z;

  auto prefetch = [&](int cc, int buf){
    int c0 = cc*CH;
    float* din = s_in + buf*TILE;
    float* dw  = s_w  + buf*WCH;
    for (int idx = tid; idx < TILE; idx += 256){
      int icl = idx/(SH*SW);
      int rem = idx - icl*(SH*SW);
      int sy  = rem/SW;
      int sx  = rem - sy*SW;
      int c   = c0+icl;
      int gy  = y0 + sy - DIL;
      int gx  = x0 + sx - DIL;
      bool ok = ((unsigned)gy < IMH) && ((unsigned)gx < IMW);
      const float* p = in_h + (size_t)(b*32 + c)*HWSZ;
      int off = ok ? (gy*IMW + gx) : 0;
      cp_async4(din + idx, p + off, ok);
    }
    int wbase = c0*288;
    for (int idx = tid; idx < WCH; idx += 256)
      cp_async4(dw + idx, g_wtd + wbase + idx, true);
  };

  unsigned long long acc[4][8];
  #pragma unroll
  for (int j=0;j<4;j++)
    #pragma unroll
    for (int o=0;o<8;o++) acc[j][o] = 0ull;

  prefetch(0, 0); cp_commit();

  for (int cc=0; cc<NC; cc++){
    if (cc+1 < NC){ prefetch(cc+1, (cc+1)&1); cp_commit(); cp_wait<1>(); }
    else          { cp_wait<0>(); }
    __syncthreads();

    const float* sin = s_in + (cc&1)*TILE;
    const float* sw  = s_w  + (cc&1)*WCH;

    for (int dy=0; dy<3; dy++){
      #pragma unroll
      for (int dx=0; dx<3; dx++){
        #pragma unroll 2
        for (int icl=0; icl<CH; icl++){
          int ibase = icl*(SH*SW) + (dy*DIL)*SW + x + dx*DIL;
          float v0 = sin[ibase + (ty4+0)*SW];
          float v1 = sin[ibase + (ty4+1)*SW];
          float v2 = sin[ibase + (ty4+2)*SW];
          float v3 = sin[ibase + (ty4+3)*SW];
          unsigned long long vv0 = pack2(v0,v0);
          unsigned long long vv1 = pack2(v1,v1);
          unsigned long long vv2 = pack2(v2,v2);
          unsigned long long vv3 = pack2(v3,v3);
          const float* wrow = &sw[(icl*9 + dy*3 + dx)*32 + oh*16];
          #pragma unroll
          for (int op=0; op<8; op++){
            unsigned long long wp = *(const unsigned long long*)(wrow + 2*op);
            ffma2(acc[0][op], vv0, wp);
            ffma2(acc[1][op], vv1, wp);
            ffma2(acc[2][op], vv2, wp);
            ffma2(acc[3][op], vv3, wp);
          }
        }
      }
    }
    __syncthreads();
  }

  const int xg = x0 + x;
  #pragma unroll
  for (int j=0;j<4;j++){
    int y = y0+ty4+j;
    #pragma unroll
    for (int op=0; op<8; op++){
      int oc = oh*16 + 2*op;
      float2 a = unpack2(acc[j][op]);
      int g0 = ((b*32+oc)*IMH + y)*IMW + xg;
      g_d1[g0]      = fmaxf(a.x, 0.f);
      g_d1[g0+HWSZ] = fmaxf(a.y, 0.f);
    }
  }
}

// ---------------- dh2 + dh3 GEMM + softmax + argmax regression ------------
// 512 threads: 16 warps, logits warp-tile = 16 oc x 2 px.
__global__ void __launch_bounds__(512) head_kernel(
    const float* __restrict__ db3,
    float* __restrict__ prob, float* __restrict__ nd)
{
  extern __shared__ float sm[];
  float* s_w3t = sm;             // 16384
  float* s_w2t = sm + 16384;     // 2048
  float* s_db3 = sm + 18432;     // 256
  float* s_d1  = sm + 18688;     // 2048
  float* s_d2  = sm + 20736;     // 4096
  float* s_l   = sm + 24832;     // 16640
  float* s_inv = sm + 41472;     // 64

  const int tid  = threadIdx.x;
  const int lane = tid & 31;
  const int g    = tid >> 5;     // 0..15
  const int y    = blockIdx.x;
  const int b    = blockIdx.y;

  for (int i = tid; i < 16384; i += 512) s_w3t[i] = g_wt3[i];
  for (int i = tid; i < 2048;  i += 512) s_w2t[i] = g_wt2[i];
  if (tid < 256) s_db3[tid] = db3[tid];
  __syncthreads();

  for (int xt = 0; xt < 5; xt++){
    int x0 = xt*64;
    for (int i = tid; i < 2048; i += 512){
      int ch = i >> 6, xp = i & 63;
      s_d1[i] = g_d1[((b*32+ch)*IMH + y)*IMW + x0 + xp];
    }
    __syncthreads();

    // d2 = relu(dh2 @ d1): thread -> px = tid&63, oc2 group (tid>>6)*8
    {
      int px  = tid & 63;
      int grp = tid >> 6;         // 0..7
      unsigned long long a2[4];
      #pragma unroll
      for (int k=0;k<4;k++) a2[k]=0ull;
      #pragma unroll 4
      for (int ic=0; ic<32; ic++){
        float v = s_d1[ic*64 + px];
        unsigned long long vv = pack2(v,v);
        const float* wr = &s_w2t[ic*64 + grp*8];
        #pragma unroll
        for (int k=0;k<4;k++){
          unsigned long long wp = *(const unsigned long long*)(wr + 2*k);
          ffma2(a2[k], vv, wp);
        }
      }
      #pragma unroll
      for (int k=0;k<4;k++){
        float2 a = unpack2(a2[k]);
        int oc2 = grp*8 + 2*k;
        s_d2[oc2*64 + px]     = fmaxf(a.x, 0.f);
        s_d2[(oc2+1)*64 + px] = fmaxf(a.y, 0.f);
      }
    }
    __syncthreads();

    // logits: warp g -> oc [g*16, g*16+16), px lane & lane+32 (f32x2 pairs)
    {
      unsigned long long a0[8], a1[8];
      #pragma unroll
      for (int k=0;k<8;k++){ a0[k]=0ull; a1[k]=0ull; }
      int x1 = lane, x2 = lane+32;
      #pragma unroll 4
      for (int ic=0; ic<64; ic++){
        float v0 = s_d2[ic*64 + x1];
        float v1 = s_d2[ic*64 + x2];
        unsigned long long vv0 = pack2(v0,v0);
        unsigned long long vv1 = pack2(v1,v1);
        const float* wr = &s_w3t[ic*256 + g*16];
        #pragma unroll
        for (int k=0;k<8;k++){
          unsigned long long wp = *(const unsigned long long*)(wr + 2*k);
          ffma2(a0[k], vv0, wp);
          ffma2(a1[k], vv1, wp);
        }
      }
      #pragma unroll
      for (int k=0;k<8;k++){
        int oc = g*16 + 2*k;
        float2 p0 = unpack2(a0[k]);
        float2 p1 = unpack2(a1[k]);
        float ba = s_db3[oc], bb = s_db3[oc+1];
        s_l[oc*65 + x1]     = p0.x + ba;
        s_l[(oc+1)*65 + x1] = p0.y + bb;
        s_l[oc*65 + x2]     = p1.x + ba;
        s_l[(oc+1)*65 + x2] = p1.y + bb;
      }
    }
    __syncthreads();

    // softmax + argmax window; warp g handles pixels [g*4, g*4+4)
    for (int p4 = 0; p4 < 4; p4++){
      int px = g*4 + p4;
      float lv[8];
      float m = -INFINITY; int mi = 0;
      #pragma unroll
      for (int k=0;k<8;k++){
        int oc = lane + k*32;
        lv[k] = s_l[oc*65 + px];
        if (lv[k] > m){ m = lv[k]; mi = oc; }
      }
      #pragma unroll
      for (int off=16; off; off>>=1){
        float om = __shfl_xor_sync(0xffffffffu, m,  off);
        int   oi = __shfl_xor_sync(0xffffffffu, mi, off);
        if (om > m || (om == m && oi < mi)){ m = om; mi = oi; }
      }
      float ssum = 0.f;
      #pragma unroll
      for (int k=0;k<8;k++){
        float e = __expf(lv[k] - m);
        s_l[(lane + k*32)*65 + px] = e;
        ssum += e;
      }
      #pragma unroll
      for (int off=16; off; off>>=1) ssum += __shfl_xor_sync(0xffffffffu, ssum, off);
      float inv = 1.f/ssum;
      __syncwarp();
      float aa = 0.f, bb = 0.f;
      if (lane < 9){
        int ocw = mi - 4 + lane;
        ocw = max(0, min(255, ocw));
        float pw = s_l[ocw*65 + px] * inv;
        aa = (float)ocw * pw;
        bb = pw;
      }
      #pragma unroll
      for (int off=16; off; off>>=1){
        aa += __shfl_xor_sync(0xffffffffu, aa, off);
        bb += __shfl_xor_sync(0xffffffffu, bb, off);
      }
      if (lane == 0){
        s_inv[px] = inv;
        nd[(b*IMH + y)*IMW + x0 + px] = (aa/(1e-6f + bb)) * (1.f/255.f);
      }
    }
    __syncthreads();

    for (int i = tid; i < 16384; i += 512){
      int oc = i >> 6, xp = i & 63;
      prob[((b*256+oc)*IMH + y)*IMW + x0 + xp] = s_l[oc*65 + xp] * s_inv[xp];
    }
    __syncthreads();
  }
}

// ---------------- launch ---------------------------------------------------
extern "C" void kernel_launch(void* const* d_in, const int* in_sizes, int n_in,
                              void* d_out, int out_size)
{
  const float* hidden = (const float*)d_in[0];
  const float* depth  = (const float*)d_in[1];
  const float* corr   = (const float*)d_in[2];
  const float* Wz  = (const float*)d_in[3];
  const float* bz  = (const float*)d_in[4];
  const float* Wr  = (const float*)d_in[5];
  const float* br  = (const float*)d_in[6];
  const float* Wq  = (const float*)d_in[7];
  const float* bq  = (const float*)d_in[8];
  const float* dh1 = (const float*)d_in[9];
  const float* dh2 = (const float*)d_in[10];
  const float* dh3 = (const float*)d_in[11];
  const float* db3 = (const float*)d_in[12];
  const float* ch1 = (const float*)d_in[13];
  const float* ch2 = (const float*)d_in[14];
  const float* cb2 = (const float*)d_in[15];

  float* out      = (float*)d_out;
  float* h_out    = out;
  float* nd_out   = h_out   + (size_t)BB*32*HWSZ;
  float* prob_out = nd_out  + (size_t)BB*HWSZ;
  float* conf_out = prob_out+ (size_t)BB*256*HWSZ;
  float* c0_out   = conf_out+ (size_t)BB*HWSZ;

  const int SM0 = 2*5120*4 + 2*(8*6*34)*4;    // 54016
  const int SM1 = 2*2560*4 + 2*(8*6*34)*4;    // 33536
  const int SM2 = 2*2560*4 + 2*(8*8*36)*4;    // 20480 + 18432 = 38912
  const int SM_D1 = (2*(8*20*36) + 2*(8*288)) * 4;   // 64512
  cudaFuncSetAttribute(uconv<0>, cudaFuncAttributeMaxDynamicSharedMemorySize, SM0);
  cudaFuncSetAttribute(uconv<1>, cudaFuncAttributeMaxDynamicSharedMemorySize, SM1);
  cudaFuncSetAttribute(uconv<2>, cudaFuncAttributeMaxDynamicSharedMemorySize, SM2);
  cudaFuncSetAttribute(conv_d1, cudaFuncAttributeMaxDynamicSharedMemorySize, SM_D1);
  cudaFuncSetAttribute(head_kernel, cudaFuncAttributeMaxDynamicSharedMemorySize, 41536*4);

  wtrans_kernel<<<dim3(64,3), 256>>>(dh1, dh2, dh3);
  wtrans_frag<<<(85760 + 255)/256, 256>>>(Wz, Wr, Wq, ch1);

  dim3 gg(IMW/32, IMH/4, BB);
  uconv<0><<<gg,128,SM0>>>(hidden, depth, corr, bz, br, hidden, nullptr, nullptr, nullptr, nullptr);
  uconv<1><<<gg,128,SM1>>>(nullptr, depth, corr, bq, nullptr, hidden, nullptr, nullptr, h_out, nullptr);
  uconv<2><<<gg,128,SM2>>>(h_out, nullptr, nullptr, nullptr, nullptr, nullptr, ch2, cb2, c0_out, conf_out);

  dim3 cg(IMW/32, IMH/16, BB);
  conv_d1<<<cg,256,SM_D1>>>(h_out);

  head_kernel<<<dim3(IMH, BB), 512, 41536*4>>>(db3, prob_out, nd_out);
}

// round 17
// speedup vs baseline: 1.7629x; 1.0102x over previous
#include <cuda_runtime.h>
#include <cuda_bf16.h>
#include <math.h>
#include <stdint.h>

#define IMH 256
#define IMW 320
#define HWSZ (IMH*IMW)
#define BB 4
#define NCT 161
#define NCHUNK 21

// frag table offsets (32-bit words)
#define QOFF   107520        // 21*5120
#define CH1OFF 161280        // QOFF + 21*2560

// ---------------- scratch (device globals; no allocation allowed) ----------
__device__ float g_z [BB*32*HWSZ];
__device__ float g_rh[BB*32*HWSZ];
__device__ float g_d1[BB*32*HWSZ];
__device__ float g_wtd[32*9*32];
__device__ float g_wt2[32*64];    // dh2^T  [ic][oc2]
__device__ float g_wt3[64*256];   // dh3^T  [ic][oc]
// B fragments: zr [21][2][5][8][32][2] | q [21][2][5][4][32][2] | ch1 [4][2][5][4][32][2]
__device__ uint32_t g_wf[171520];

__device__ __forceinline__ float sigmoidf_(float v){ return 1.f/(1.f+__expf(-v)); }

// ---- packed fp32x2 helpers ------------------------------------------------
__device__ __forceinline__ unsigned long long pack2(float a, float b){
  unsigned long long r; asm("mov.b64 %0,{%1,%2};":"=l"(r):"f"(a),"f"(b)); return r;
}
__device__ __forceinline__ void ffma2(unsigned long long& d, unsigned long long a, unsigned long long b){
  asm("fma.rn.f32x2 %0, %1, %2, %0;":"+l"(d):"l"(a),"l"(b));
}
__device__ __forceinline__ float2 unpack2(unsigned long long v){
  float2 r; asm("mov.b64 {%0,%1}, %2;":"=f"(r.x),"=f"(r.y):"l"(v)); return r;
}

// ---- cp.async helpers -----------------------------------------------------
__device__ __forceinline__ void cp_async4(float* smem_dst, const float* gsrc, bool valid){
  unsigned int d = (unsigned int)__cvta_generic_to_shared(smem_dst);
  int sz = valid ? 4 : 0;
  asm volatile("cp.async.ca.shared.global [%0], [%1], 4, %2;\n" :: "r"(d), "l"(gsrc), "r"(sz));
}
__device__ __forceinline__ void cp_async16(void* smem_dst, const void* gsrc){
  unsigned int d = (unsigned int)__cvta_generic_to_shared(smem_dst);
  asm volatile("cp.async.cg.shared.global [%0], [%1], 16;\n" :: "r"(d), "l"(gsrc));
}
__device__ __forceinline__ void cp_commit(){ asm volatile("cp.async.commit_group;\n"); }
template<int N> __device__ __forceinline__ void cp_wait(){ asm volatile("cp.async.wait_group %0;\n"::"n"(N)); }

// ---- bf16 pack: lower 16 = bf16(lo_elem), upper 16 = bf16(hi_elem) --------
__device__ __forceinline__ uint32_t packbf(float lo_elem, float hi_elem){
  uint32_t r; asm("cvt.rn.bf16x2.f32 %0, %1, %2;" : "=r"(r) : "f"(hi_elem), "f"(lo_elem)); return r;
}

// ---- warp mma m16n8k16 bf16 ----------------------------------------------
__device__ __forceinline__ void mma_bf16(float& d0,float& d1,float& d2,float& d3,
    uint32_t a0,uint32_t a1,uint32_t a2,uint32_t a3, uint32_t b0,uint32_t b1){
  asm volatile("mma.sync.aligned.m16n8k16.row.col.f32.bf16.bf16.f32 "
    "{%0,%1,%2,%3}, {%4,%5,%6,%7}, {%8,%9}, {%0,%1,%2,%3};"
    : "+f"(d0),"+f"(d1),"+f"(d2),"+f"(d3)
    : "r"(a0),"r"(a1),"r"(a2),"r"(a3),"r"(b0),"r"(b1));
}

// ---------------- head weight transposes (fp32 path) -----------------------
__global__ void wtrans_kernel(const float* __restrict__ dh1,
                              const float* __restrict__ dh2, const float* __restrict__ dh3){
  int t = blockIdx.y;
  int idx = blockIdx.x*256 + threadIdx.x;
  if (t==0){
    if (idx < 32*288){
      int ic = idx/288; int r = idx - ic*288; int tap = r>>5; int oc = r&31;
      g_wtd[idx] = dh1[(oc*32+ic)*9+tap];
    }
  } else if (t==1){
    if (idx < 2048) g_wt2[idx] = dh2[(idx&63)*32 + (idx>>6)];
  } else {
    if (idx < 16384) g_wt3[idx] = dh3[(idx&255)*64 + (idx>>8)];
  }
}

// ---------------- conv weights -> hi/lo bf16 B-fragments -------------------
// zr: nb0-3 = Wz, nb4-7 = Wr | q: nb0-3 = Wq | ch1: nb0-3 = ch1
__global__ void wtrans_frag(const float* __restrict__ Wz, const float* __restrict__ Wr,
                            const float* __restrict__ Wq, const float* __restrict__ ch1){
  int idx = blockIdx.x*256 + threadIdx.x;   // 53760 + 26880 + 5120 = 85760 entries
  if (idx >= 85760) return;
  const float* W; int cin, oc, cc, ver, s, nb, lane;
  uint32_t* dst;
  if (idx < 53760){
    cc = idx/2560; int r = idx%2560;
    ver = r/1280; r %= 1280; s = r/256; r %= 256; nb = r/32; lane = r%32;
    int g = lane>>2;
    W = (nb<4) ? Wz : Wr; cin = NCT; oc = (nb&3)*8 + g;
    dst = g_wf + cc*5120 + (((ver*5+s)*8+nb)*32+lane)*2;
  } else if (idx < 80640){
    int i2 = idx - 53760;
    cc = i2/1280; int r = i2%1280;
    ver = r/640; r %= 640; s = r/128; r %= 128; nb = r/32; lane = r%32;
    int g = lane>>2;
    W = Wq; cin = NCT; oc = nb*8 + g;
    dst = g_wf + QOFF + cc*2560 + (((ver*5+s)*4+nb)*32+lane)*2;
  } else {
    int i2 = idx - 80640;
    cc = i2/1280; int r = i2%1280;
    ver = r/640; r %= 640; s = r/128; r %= 128; nb = r/32; lane = r%32;
    int g = lane>>2;
    W = ch1; cin = 32; oc = nb*8 + g;
    dst = g_wf + CH1OFF + cc*2560 + (((ver*5+s)*4+nb)*32+lane)*2;
  }
  int tt = lane & 3;
  auto wval = [&](int k)->float{
    if (k >= 72) return 0.f;
    int ic = cc*8 + k/9;
    if (ic >= cin) return 0.f;
    return W[(oc*cin+ic)*9 + (k%9)];
  };
  int k0 = s*16 + 2*tt;
  float w00 = wval(k0),   w01 = wval(k0+1);
  float w10 = wval(k0+8), w11 = wval(k0+9);
  uint32_t b0, b1;
  if (ver == 0){
    b0 = packbf(w00, w01);
    b1 = packbf(w10, w11);
  } else {
    float h00 = __bfloat162float(__float2bfloat16(w00));
    float h01 = __bfloat162float(__float2bfloat16(w01));
    float h10 = __bfloat162float(__float2bfloat16(w10));
    float h11 = __bfloat162float(__float2bfloat16(w11));
    b0 = packbf(w00-h00, w01-h01);
    b1 = packbf(w10-h10, w11-h11);
  }
  dst[0] = b0; dst[1] = b1;
}

// ============= convs via warp-mma bf16 (hi/lo split) ======================
// MODE 0: fused z+r (N=64, DIL=1, CIN=161): g_z, g_rh
// MODE 1: q        (N=32, DIL=1, CIN=161): h -> out
// MODE 2: conf head (N=32, DIL=2, CIN=32): c0 -> out, conf -> out2
// CTA 128 thr / 4 warps; tile 32x4 px (warp = tile row), M=128.
// MMA issue is term-major within groups of 4 nb (dep distance 4); per-dd
// accumulation order hh->hl->lh is unchanged => bit-identical numerics.
template<int MODE>
__global__ void __launch_bounds__(128, (MODE==0)?3:5) uconv(
    const float* __restrict__ in0, const float* __restrict__ depth,
    const float* __restrict__ corr, const float* __restrict__ bias,
    const float* __restrict__ bias2, const float* __restrict__ hidden,
    const float* __restrict__ aux, const float* __restrict__ aux2,
    float* __restrict__ out, float* __restrict__ out2)
{
  constexpr int DIL  = (MODE==2) ? 2 : 1;
  constexpr int CIN  = (MODE==2) ? 32 : NCT;
  constexpr int NCH  = (MODE==2) ? 4 : NCHUNK;
  constexpr int NB   = (MODE==0) ? 8 : 4;
  constexpr int SH   = 4 + 2*DIL;
  constexpr int SW   = 32 + 2*DIL;
  constexpr int RAWSZ= 8*SH*SW;
  constexpr int WRDS = NB*640;
  constexpr int LOOF = NB*320;

  extern __shared__ __align__(16) unsigned char smx[];
  uint32_t* s_wf = (uint32_t*)smx;
  float*    s_raw= (float*)(smx + 2*WRDS*4);

  const int tid  = threadIdx.x;
  const int wrp  = tid >> 5;
  const int lane = tid & 31;
  const int g    = lane >> 2;
  const int t    = lane & 3;
  const int x0 = blockIdx.x*32, y0 = blockIdx.y*4, b = blockIdx.z;

  const float* i0 = (MODE==1) ? (const float*)g_rh : in0;
  const uint32_t* wsrc = (MODE==0) ? g_wf : ((MODE==1) ? (g_wf + QOFF) : (g_wf + CH1OFF));

  int offA[5][4];
  #pragma unroll
  for (int s=0;s<5;s++){
    #pragma unroll
    for (int j=0;j<4;j++){
      int k = s*16 + 2*t + (j&1) + (j>>1)*8;
      offA[s][j] = (k<72) ? ((k/9)*(SH*SW) + ((k%9)/3)*DIL*SW + ((k%9)%3)*DIL) : 0;
    }
  }

  auto prefetch = [&](int cc, int buf){
    float* din = s_raw + buf*RAWSZ;
    for (int idx = tid; idx < RAWSZ; idx += 128){
      int icl = idx/(SH*SW);
      int rem = idx - icl*(SH*SW);
      int sy  = rem/SW;
      int sx  = rem - sy*SW;
      int c   = cc*8 + icl;
      int gy  = y0 + sy - DIL;
      int gx  = x0 + sx - DIL;
      bool ok = (c < CIN) && ((unsigned)gy < IMH) && ((unsigned)gx < IMW);
      int cs  = ok ? c : 0;
      const float* p;
      if (MODE==2)       p = in0  + (size_t)(b*32 + cs)*HWSZ;
      else if (cs < 32)  p = i0   + (size_t)(b*32 + cs)*HWSZ;
      else if (cs == 32) p = depth+ (size_t)b*HWSZ;
      else               p = corr + (size_t)(b*128 + (cs-33))*HWSZ;
      int off = ok ? (gy*IMW + gx) : 0;
      cp_async4(din + idx, p + off, ok);
    }
    const uint4* gsrc = (const uint4*)(wsrc + (size_t)cc*WRDS);
    uint4* dst = (uint4*)(s_wf + buf*WRDS);
    for (int i = tid; i < WRDS/4; i += 128)
      cp_async16(dst + i, gsrc + i);
  };

  float D[2*NB*4];
  #pragma unroll
  for (int i=0;i<2*NB*4;i++) D[i]=0.f;

  prefetch(0, 0); cp_commit();

  for (int cc = 0; cc < NCH; cc++){
    cp_wait<0>();
    __syncthreads();
    if (cc+1 < NCH){ prefetch(cc+1, (cc+1)&1); cp_commit(); }

    const float* raw = s_raw + (cc&1)*RAWSZ + wrp*SW;
    const uint32_t* wf = s_wf + (cc&1)*WRDS;

    #pragma unroll
    for (int s=0;s<5;s++){
      #pragma unroll
      for (int mb=0;mb<2;mb++){
        const float* pA = raw + mb*16 + g;
        const float* pB = pA + 8;
        float vA0 = pA[offA[s][0]], vA1 = pA[offA[s][1]];
        float vB0 = pB[offA[s][0]], vB1 = pB[offA[s][1]];
        uint32_t ah0 = packbf(vA0, vA1);
        uint32_t ah1 = packbf(vB0, vB1);
        float hA0 = __uint_as_float(ah0<<16), hA1 = __uint_as_float(ah0 & 0xffff0000u);
        float hB0 = __uint_as_float(ah1<<16), hB1 = __uint_as_float(ah1 & 0xffff0000u);
        uint32_t al0 = packbf(vA0-hA0, vA1-hA1);
        uint32_t al1 = packbf(vB0-hB0, vB1-hB1);
        uint32_t ah2=0, ah3=0, al2=0, al3=0;
        if (s < 4){
          float wA0 = pA[offA[s][2]], wA1 = pA[offA[s][3]];
          float wB0 = pB[offA[s][2]], wB1 = pB[offA[s][3]];
          ah2 = packbf(wA0, wA1);
          ah3 = packbf(wB0, wB1);
          float qA0 = __uint_as_float(ah2<<16), qA1 = __uint_as_float(ah2 & 0xffff0000u);
          float qB0 = __uint_as_float(ah3<<16), qB1 = __uint_as_float(ah3 & 0xffff0000u);
          al2 = packbf(wA0-qA0, wA1-qA1);
          al3 = packbf(wB0-qB0, wB1-qB1);
        }
        #pragma unroll
        for (int grp=0; grp<NB/4; grp++){
          uint2 bh[4], bl[4];
          #pragma unroll
          for (int j=0;j<4;j++){
            int nb = grp*4 + j;
            bh[j] = *(const uint2*)(wf + (s*NB+nb)*64 + lane*2);
            bl[j] = *(const uint2*)(wf + LOOF + (s*NB+nb)*64 + lane*2);
          }
          #pragma unroll
          for (int j=0;j<4;j++){
            float* dd = &D[(mb*NB+grp*4+j)*4];
            mma_bf16(dd[0],dd[1],dd[2],dd[3], ah0,ah1,ah2,ah3, bh[j].x,bh[j].y);
          }
          #pragma unroll
          for (int j=0;j<4;j++){
            float* dd = &D[(mb*NB+grp*4+j)*4];
            mma_bf16(dd[0],dd[1],dd[2],dd[3], ah0,ah1,ah2,ah3, bl[j].x,bl[j].y);
          }
          #pragma unroll
          for (int j=0;j<4;j++){
            float* dd = &D[(mb*NB+grp*4+j)*4];
            mma_bf16(dd[0],dd[1],dd[2],dd[3], al0,al1,al2,al3, bh[j].x,bh[j].y);
          }
        }
      }
    }
  }

  // epilogue. D frag: d0:(g,2t) d1:(g,2t+1) d2:(g+8,2t) d3:(g+8,2t+1)
  const int y = y0 + wrp;
  if (MODE==0){
    #pragma unroll
    for (int mb=0;mb<2;mb++){
      int xA = x0 + mb*16 + g;
      #pragma unroll
      for (int nb=0;nb<8;nb++){
        float* dd = &D[(mb*8+nb)*4];
        int oc0 = (nb&3)*8 + 2*t;
        float b0v = (nb<4) ? __ldg(bias+oc0)   : __ldg(bias2+oc0);
        float b1v = (nb<4) ? __ldg(bias+oc0+1) : __ldg(bias2+oc0+1);
        int gi0 = ((b*32+oc0)*IMH + y)*IMW + xA;
        int gi1 = gi0 + HWSZ;
        if (nb<4){
          g_z[gi0]   = sigmoidf_(dd[0] + b0v);
          g_z[gi1]   = sigmoidf_(dd[1] + b1v);
          g_z[gi0+8] = sigmoidf_(dd[2] + b0v);
          g_z[gi1+8] = sigmoidf_(dd[3] + b1v);
        } else {
          g_rh[gi0]   = sigmoidf_(dd[0] + b0v) * __ldg(hidden+gi0);
          g_rh[gi1]   = sigmoidf_(dd[1] + b1v) * __ldg(hidden+gi1);
          g_rh[gi0+8] = sigmoidf_(dd[2] + b0v) * __ldg(hidden+gi0+8);
          g_rh[gi1+8] = sigmoidf_(dd[3] + b1v) * __ldg(hidden+gi1+8);
        }
      }
    }
  } else if (MODE==1){
    #pragma unroll
    for (int mb=0;mb<2;mb++){
      int xA = x0 + mb*16 + g;
      #pragma unroll
      for (int nb=0;nb<4;nb++){
        float* dd = &D[(mb*4+nb)*4];
        int oc0 = nb*8 + 2*t;
        float b0v = __ldg(bias+oc0), b1v = __ldg(bias+oc0+1);
        int gi0 = ((b*32+oc0)*IMH + y)*IMW + xA;
        int gi1 = gi0 + HWSZ;
        #pragma unroll
        for (int e=0;e<4;e++){
          int gi = (e&1) ? gi1 : gi0;
          gi += (e>>1)*8;
          float v = dd[e] + ((e&1)?b1v:b0v);
          float q  = tanhf(v);
          float z  = g_z[gi];
          float h0 = __ldg(hidden+gi);
          out[gi] = h0 + z*(q - h0);
        }
      }
    }
  } else {
    float cb = __ldg(aux2);
    #pragma unroll
    for (int mb=0;mb<2;mb++){
      int xA = x0 + mb*16 + g;
      float cr0 = 0.f, cr1 = 0.f;
      #pragma unroll
      for (int nb=0;nb<4;nb++){
        float* dd = &D[(mb*4+nb)*4];
        int oc0 = nb*8 + 2*t;
        float c0w = __ldg(aux+oc0), c1w = __ldg(aux+oc0+1);
        cr0 = fmaf(c0w, fmaxf(dd[0],0.f), fmaf(c1w, fmaxf(dd[1],0.f), cr0));
        cr1 = fmaf(c0w, fmaxf(dd[2],0.f), fmaf(c1w, fmaxf(dd[3],0.f), cr1));
      }
      cr0 += __shfl_xor_sync(0xffffffffu, cr0, 1);
      cr0 += __shfl_xor_sync(0xffffffffu, cr0, 2);
      cr1 += __shfl_xor_sync(0xffffffffu, cr1, 1);
      cr1 += __shfl_xor_sync(0xffffffffu, cr1, 2);
      if (t == 0){
        int p0 = (b*IMH + y)*IMW + xA;
        float v0 = cr0 + cb, v1 = cr1 + cb;
        out [p0]   = v0;  out2[p0]   = sigmoidf_(v0);
        out [p0+8] = v1;  out2[p0+8] = sigmoidf_(v1);
      }
    }
  }
}

// ============= d1 conv (Cin=32, dil=2) — fp32 f32x2 (argmax-critical) =====
__global__ void __launch_bounds__(256,2) conv_d1(const float* __restrict__ in_h)
{
  constexpr int DIL = 2;
  constexpr int SH  = 20;
  constexpr int SW  = 36;
  constexpr int CH  = 8;
  constexpr int TILE = CH*SH*SW;
  constexpr int WCH  = CH*288;
  constexpr int NC   = 4;

  extern __shared__ float sm[];
  float* s_in  = sm;
  float* s_w   = sm + 2*TILE;

  const int tid = threadIdx.x;
  const int x   = tid & 31;
  const int ty  = (tid >> 5) & 3;
  const int oh  = tid >> 7;
  const int ty4 = ty*4;
  const int x0  = blockIdx.x*32;
  const int y0  = blockIdx.y*16;
  const int b   = blockIdx.z;

  auto prefetch = [&](int cc, int buf){
    int c0 = cc*CH;
    float* din = s_in + buf*TILE;
    float* dw  = s_w  + buf*WCH;
    for (int idx = tid; idx < TILE; idx += 256){
      int icl = idx/(SH*SW);
      int rem = idx - icl*(SH*SW);
      int sy  = rem/SW;
      int sx  = rem - sy*SW;
      int c   = c0+icl;
      int gy  = y0 + sy - DIL;
      int gx  = x0 + sx - DIL;
      bool ok = ((unsigned)gy < IMH) && ((unsigned)gx < IMW);
      const float* p = in_h + (size_t)(b*32 + c)*HWSZ;
      int off = ok ? (gy*IMW + gx) : 0;
      cp_async4(din + idx, p + off, ok);
    }
    int wbase = c0*288;
    for (int idx = tid; idx < WCH; idx += 256)
      cp_async4(dw + idx, g_wtd + wbase + idx, true);
  };

  unsigned long long acc[4][8];
  #pragma unroll
  for (int j=0;j<4;j++)
    #pragma unroll
    for (int o=0;o<8;o++) acc[j][o] = 0ull;

  prefetch(0, 0); cp_commit();

  for (int cc=0; cc<NC; cc++){
    if (cc+1 < NC){ prefetch(cc+1, (cc+1)&1); cp_commit(); cp_wait<1>(); }
    else          { cp_wait<0>(); }
    __syncthreads();

    const float* sin = s_in + (cc&1)*TILE;
    const float* sw  = s_w  + (cc&1)*WCH;

    for (int dy=0; dy<3; dy++){
      #pragma unroll
      for (int dx=0; dx<3; dx++){
        #pragma unroll 2
        for (int icl=0; icl<CH; icl++){
          int ibase = icl*(SH*SW) + (dy*DIL)*SW + x + dx*DIL;
          float v0 = sin[ibase + (ty4+0)*SW];
          float v1 = sin[ibase + (ty4+1)*SW];
          float v2 = sin[ibase + (ty4+2)*SW];
          float v3 = sin[ibase + (ty4+3)*SW];
          unsigned long long vv0 = pack2(v0,v0);
          unsigned long long vv1 = pack2(v1,v1);
          unsigned long long vv2 = pack2(v2,v2);
          unsigned long long vv3 = pack2(v3,v3);
          const float* wrow = &sw[(icl*9 + dy*3 + dx)*32 + oh*16];
          #pragma unroll
          for (int op=0; op<8; op++){
            unsigned long long wp = *(const unsigned long long*)(wrow + 2*op);
            ffma2(acc[0][op], vv0, wp);
            ffma2(acc[1][op], vv1, wp);
            ffma2(acc[2][op], vv2, wp);
            ffma2(acc[3][op], vv3, wp);
          }
        }
      }
    }
    __syncthreads();
  }

  const int xg = x0 + x;
  #pragma unroll
  for (int j=0;j<4;j++){
    int y = y0+ty4+j;
    #pragma unroll
    for (int op=0; op<8; op++){
      int oc = oh*16 + 2*op;
      float2 a = unpack2(acc[j][op]);
      int g0 = ((b*32+oc)*IMH + y)*IMW + xg;
      g_d1[g0]      = fmaxf(a.x, 0.f);
      g_d1[g0+HWSZ] = fmaxf(a.y, 0.f);
    }
  }
}

// ---------------- dh2 + dh3 GEMM + softmax + argmax regression ------------
// 512 threads: 16 warps, logits warp-tile = 16 oc x 2 px.
__global__ void __launch_bounds__(512) head_kernel(
    const float* __restrict__ db3,
    float* __restrict__ prob, float* __restrict__ nd)
{
  extern __shared__ float sm[];
  float* s_w3t = sm;             // 16384
  float* s_w2t = sm + 16384;     // 2048
  float* s_db3 = sm + 18432;     // 256
  float* s_d1  = sm + 18688;     // 2048
  float* s_d2  = sm + 20736;     // 4096
  float* s_l   = sm + 24832;     // 16640
  float* s_inv = sm + 41472;     // 64

  const int tid  = threadIdx.x;
  const int lane = tid & 31;
  const int g    = tid >> 5;     // 0..15
  const int y    = blockIdx.x;
  const int b    = blockIdx.y;

  for (int i = tid; i < 16384; i += 512) s_w3t[i] = g_wt3[i];
  for (int i = tid; i < 2048;  i += 512) s_w2t[i] = g_wt2[i];
  if (tid < 256) s_db3[tid] = db3[tid];
  __syncthreads();

  for (int xt = 0; xt < 5; xt++){
    int x0 = xt*64;
    for (int i = tid; i < 2048; i += 512){
      int ch = i >> 6, xp = i & 63;
      s_d1[i] = g_d1[((b*32+ch)*IMH + y)*IMW + x0 + xp];
    }
    __syncthreads();

    // d2 = relu(dh2 @ d1): thread -> px = tid&63, oc2 group (tid>>6)*8
    {
      int px  = tid & 63;
      int grp = tid >> 6;         // 0..7
      unsigned long long a2[4];
      #pragma unroll
      for (int k=0;k<4;k++) a2[k]=0ull;
      #pragma unroll 4
      for (int ic=0; ic<32; ic++){
        float v = s_d1[ic*64 + px];
        unsigned long long vv = pack2(v,v);
        const float* wr = &s_w2t[ic*64 + grp*8];
        #pragma unroll
        for (int k=0;k<4;k++){
          unsigned long long wp = *(const unsigned long long*)(wr + 2*k);
          ffma2(a2[k], vv, wp);
        }
      }
      #pragma unroll
      for (int k=0;k<4;k++){
        float2 a = unpack2(a2[k]);
        int oc2 = grp*8 + 2*k;
        s_d2[oc2*64 + px]     = fmaxf(a.x, 0.f);
        s_d2[(oc2+1)*64 + px] = fmaxf(a.y, 0.f);
      }
    }
    __syncthreads();

    // logits: warp g -> oc [g*16, g*16+16), px lane & lane+32 (f32x2 pairs)
    {
      unsigned long long a0[8], a1[8];
      #pragma unroll
      for (int k=0;k<8;k++){ a0[k]=0ull; a1[k]=0ull; }
      int x1 = lane, x2 = lane+32;
      #pragma unroll 4
      for (int ic=0; ic<64; ic++){
        float v0 = s_d2[ic*64 + x1];
        float v1 = s_d2[ic*64 + x2];
        unsigned long long vv0 = pack2(v0,v0);
        unsigned long long vv1 = pack2(v1,v1);
        const float* wr = &s_w3t[ic*256 + g*16];
        #pragma unroll
        for (int k=0;k<8;k++){
          unsigned long long wp = *(const unsigned long long*)(wr + 2*k);
          ffma2(a0[k], vv0, wp);
          ffma2(a1[k], vv1, wp);
        }
      }
      #pragma unroll
      for (int k=0;k<8;k++){
        int oc = g*16 + 2*k;
        float2 p0 = unpack2(a0[k]);
        float2 p1 = unpack2(a1[k]);
        float ba = s_db3[oc], bb = s_db3[oc+1];
        s_l[oc*65 + x1]     = p0.x + ba;
        s_l[(oc+1)*65 + x1] = p0.y + bb;
        s_l[oc*65 + x2]     = p1.x + ba;
        s_l[(oc+1)*65 + x2] = p1.y + bb;
      }
    }
    __syncthreads();

    // softmax + argmax window; warp g handles pixels [g*4, g*4+4)
    for (int p4 = 0; p4 < 4; p4++){
      int px = g*4 + p4;
      float lv[8];
      float m = -INFINITY; int mi = 0;
      #pragma unroll
      for (int k=0;k<8;k++){
        int oc = lane + k*32;
        lv[k] = s_l[oc*65 + px];
        if (lv[k] > m){ m = lv[k]; mi = oc; }
      }
      #pragma unroll
      for (int off=16; off; off>>=1){
        float om = __shfl_xor_sync(0xffffffffu, m,  off);
        int   oi = __shfl_xor_sync(0xffffffffu, mi, off);
        if (om > m || (om == m && oi < mi)){ m = om; mi = oi; }
      }
      float ssum = 0.f;
      #pragma unroll
      for (int k=0;k<8;k++){
        float e = __expf(lv[k] - m);
        s_l[(lane + k*32)*65 + px] = e;
        ssum += e;
      }
      #pragma unroll
      for (int off=16; off; off>>=1) ssum += __shfl_xor_sync(0xffffffffu, ssum, off);
      float inv = 1.f/ssum;
      __syncwarp();
      float aa = 0.f, bb = 0.f;
      if (lane < 9){
        int ocw = mi - 4 + lane;
        ocw = max(0, min(255, ocw));
        float pw = s_l[ocw*65 + px] * inv;
        aa = (float)ocw * pw;
        bb = pw;
      }
      #pragma unroll
      for (int off=16; off; off>>=1){
        aa += __shfl_xor_sync(0xffffffffu, aa, off);
        bb += __shfl_xor_sync(0xffffffffu, bb, off);
      }
      if (lane == 0){
        s_inv[px] = inv;
        nd[(b*IMH + y)*IMW + x0 + px] = (aa/(1e-6f + bb)) * (1.f/255.f);
      }
    }
    __syncthreads();

    for (int i = tid; i < 16384; i += 512){
      int oc = i >> 6, xp = i & 63;
      prob[((b*256+oc)*IMH + y)*IMW + x0 + xp] = s_l[oc*65 + xp] * s_inv[xp];
    }
    __syncthreads();
  }
}

// ---------------- launch ---------------------------------------------------
extern "C" void kernel_launch(void* const* d_in, const int* in_sizes, int n_in,
                              void* d_out, int out_size)
{
  const float* hidden = (const float*)d_in[0];
  const float* depth  = (const float*)d_in[1];
  const float* corr   = (const float*)d_in[2];
  const float* Wz  = (const float*)d_in[3];
  const float* bz  = (const float*)d_in[4];
  const float* Wr  = (const float*)d_in[5];
  const float* br  = (const float*)d_in[6];
  const float* Wq  = (const float*)d_in[7];
  const float* bq  = (const float*)d_in[8];
  const float* dh1 = (const float*)d_in[9];
  const float* dh2 = (const float*)d_in[10];
  const float* dh3 = (const float*)d_in[11];
  const float* db3 = (const float*)d_in[12];
  const float* ch1 = (const float*)d_in[13];
  const float* ch2 = (const float*)d_in[14];
  const float* cb2 = (const float*)d_in[15];

  float* out      = (float*)d_out;
  float* h_out    = out;
  float* nd_out   = h_out   + (size_t)BB*32*HWSZ;
  float* prob_out = nd_out  + (size_t)BB*HWSZ;
  float* conf_out = prob_out+ (size_t)BB*256*HWSZ;
  float* c0_out   = conf_out+ (size_t)BB*HWSZ;

  const int SM0 = 2*5120*4 + 2*(8*6*34)*4;    // 54016
  const int SM1 = 2*2560*4 + 2*(8*6*34)*4;    // 33536
  const int SM2 = 2*2560*4 + 2*(8*8*36)*4;    // 38912
  const int SM_D1 = (2*(8*20*36) + 2*(8*288)) * 4;   // 64512
  cudaFuncSetAttribute(uconv<0>, cudaFuncAttributeMaxDynamicSharedMemorySize, SM0);
  cudaFuncSetAttribute(uconv<1>, cudaFuncAttributeMaxDynamicSharedMemorySize, SM1);
  cudaFuncSetAttribute(uconv<2>, cudaFuncAttributeMaxDynamicSharedMemorySize, SM2);
  cudaFuncSetAttribute(conv_d1, cudaFuncAttributeMaxDynamicSharedMemorySize, SM_D1);
  cudaFuncSetAttribute(head_kernel, cudaFuncAttributeMaxDynamicSharedMemorySize, 41536*4);

  wtrans_kernel<<<dim3(64,3), 256>>>(dh1, dh2, dh3);
  wtrans_frag<<<(85760 + 255)/256, 256>>>(Wz, Wr, Wq, ch1);

  dim3 gg(IMW/32, IMH/4, BB);
  uconv<0><<<gg,128,SM0>>>(hidden, depth, corr, bz, br, hidden, nullptr, nullptr, nullptr, nullptr);
  uconv<1><<<gg,128,SM1>>>(nullptr, depth, corr, bq, nullptr, hidden, nullptr, nullptr, h_out, nullptr);
  uconv<2><<<gg,128,SM2>>>(h_out, nullptr, nullptr, nullptr, nullptr, nullptr, ch2, cb2, c0_out, conf_out);

  dim3 cg(IMW/32, IMH/16, BB);
  conv_d1<<<cg,256,SM_D1>>>(h_out);

  head_kernel<<<dim3(IMH, BB), 512, 41536*4>>>(db3, prob_out, nd_out);
}